// round 1
// baseline (speedup 1.0000x reference)
#include <cuda_runtime.h>
#include <cuda_bf16.h>
#include <math.h>

// ---------------------------------------------------------------------------
// Decoder: ASPP (3x conv1x1+BN+ReLU, bilinear upsample, conv3x3+BN+ReLU)
// followed by LIIF local-ensemble query with MLP 98->128->128->1.
//
// Algorithmic restructure: G[p][k] = feat[p] @ W0[0:96,k] + b0[k] precomputed
// per feature pixel; per query-shift only the rank-2 rel contribution + relu +
// a 128x128 GEMM remain.
// ---------------------------------------------------------------------------

#define HF 256            // feat grid 256x256
#define FC 96             // fused channels
#define UQ 128            // mlp hidden
#define QRES 512          // query grid

// scratch (device globals; no allocation allowed)
__device__ float g_cat [HF*HF*FC];     // concat(a2, up(a4), up(a32))
__device__ float g_feat[HF*HF*FC];     // after 3x3 conv
__device__ float g_a4  [128*128*32];
__device__ float g_a32 [16*16*32];
__device__ float g_G   [HF*HF*UQ];     // feat @ W0_feat + b0

// ---------------------------------------------------------------------------
// 1x1 conv + folded BN + ReLU, Cout=32. One thread per pixel.
// ---------------------------------------------------------------------------
__global__ void conv1x1_kernel(const float* __restrict__ in,
                               const float* __restrict__ w,
                               const float* __restrict__ s,
                               const float* __restrict__ b,
                               float* __restrict__ out,
                               int HW, int Cin, int ostride, int ocoff) {
    __shared__ float wsm[256 * 32];
    __shared__ float ssm[32], bsm[32];
    for (int i = threadIdx.x; i < Cin * 32; i += blockDim.x) wsm[i] = w[i];
    if (threadIdx.x < 32) { ssm[threadIdx.x] = s[threadIdx.x]; bsm[threadIdx.x] = b[threadIdx.x]; }
    __syncthreads();
    int p = blockIdx.x * blockDim.x + threadIdx.x;
    if (p >= HW) return;
    const float* ip = in + (size_t)p * Cin;
    float acc[32];
#pragma unroll
    for (int j = 0; j < 32; j++) acc[j] = 0.f;
    for (int ci = 0; ci < Cin; ci++) {
        float v = __ldg(ip + ci);
        const float* wr = wsm + ci * 32;
#pragma unroll
        for (int j = 0; j < 32; j++) acc[j] = fmaf(v, wr[j], acc[j]);
    }
    float* op = out + (size_t)p * ostride + ocoff;
#pragma unroll
    for (int j = 0; j < 32; j++)
        op[j] = fmaxf(fmaf(acc[j], ssm[j], bsm[j]), 0.f);
}

// ---------------------------------------------------------------------------
// bilinear upsample a4 (128->256) and a32 (16->256) into cat channels 32..95
// jax.image.resize 'bilinear': src = (o+0.5)*in/out - 0.5, clamped indices.
// ---------------------------------------------------------------------------
__device__ __forceinline__ float bilerp(const float* A, int N, int c,
                                        float sy, float sx) {
    int y0 = (int)floorf(sy); float wy = sy - (float)y0;
    int x0 = (int)floorf(sx); float wx = sx - (float)x0;
    int y0c = max(y0, 0), y1c = min(y0 + 1, N - 1);
    int x0c = max(x0, 0), x1c = min(x0 + 1, N - 1);
    float v00 = A[((size_t)y0c * N + x0c) * 32 + c];
    float v01 = A[((size_t)y0c * N + x1c) * 32 + c];
    float v10 = A[((size_t)y1c * N + x0c) * 32 + c];
    float v11 = A[((size_t)y1c * N + x1c) * 32 + c];
    return (1.f - wy) * ((1.f - wx) * v00 + wx * v01)
         + wy        * ((1.f - wx) * v10 + wx * v11);
}

__global__ void upsample_kernel() {
    int idx = blockIdx.x * blockDim.x + threadIdx.x;  // 256*256*64
    if (idx >= HF * HF * 64) return;
    int c = idx & 63;
    int p = idx >> 6;
    int oy = p >> 8, ox = p & 255;
    if (c < 32) {
        float sy = (oy + 0.5f) * 0.5f - 0.5f;
        float sx = (ox + 0.5f) * 0.5f - 0.5f;
        g_cat[(size_t)p * FC + 32 + c] = bilerp(g_a4, 128, c, sy, sx);
    } else {
        int cc = c - 32;
        float sy = (oy + 0.5f) * 0.0625f - 0.5f;
        float sx = (ox + 0.5f) * 0.0625f - 0.5f;
        g_cat[(size_t)p * FC + 64 + cc] = bilerp(g_a32, 16, cc, sy, sx);
    }
}

// ---------------------------------------------------------------------------
// 3x3 conv 96->96 + BN + ReLU, SAME padding.
// CTA: 16x16 pixel tile, 512 threads (pixel x 2 out-channel halves of 48).
// Input-channel chunks of 8 staged through smem (channel-major to avoid
// bank conflicts on the x-contiguous reads).
// ---------------------------------------------------------------------------
__global__ __launch_bounds__(512) void conv3x3_kernel(const float* __restrict__ wf,
                                                      const float* __restrict__ sf,
                                                      const float* __restrict__ bf) {
    __shared__ float ws[9 * 8 * 96];     // [kpos][ci][co]
    __shared__ float ins[8 * 18 * 18];   // [ci][y][x]
    int t = threadIdx.x;
    int ty0 = blockIdx.y * 16, tx0 = blockIdx.x * 16;
    int pix = t & 255, half = t >> 8;
    int py = pix >> 4, px = pix & 15;
    int cobase = half * 48;
    float acc[48];
#pragma unroll
    for (int j = 0; j < 48; j++) acc[j] = 0.f;

    for (int ch = 0; ch < 12; ch++) {
        int ci0 = ch * 8;
        for (int i = t; i < 9 * 8 * 96; i += 512) {
            int kpos = i / (8 * 96);
            int r = i - kpos * 8 * 96;
            int ci = r / 96, co = r - ci * 96;
            ws[i] = wf[((size_t)kpos * 96 + ci0 + ci) * 96 + co];
        }
        for (int i = t; i < 8 * 324; i += 512) {
            int ci = i / 324; int r = i - ci * 324;
            int iy = r / 18, ix = r - iy * 18;
            int gy = ty0 + iy - 1, gx = tx0 + ix - 1;
            float v = 0.f;
            if (gy >= 0 && gy < HF && gx >= 0 && gx < HF)
                v = g_cat[((size_t)gy * HF + gx) * FC + ci0 + ci];
            ins[i] = v;
        }
        __syncthreads();
#pragma unroll
        for (int kpos = 0; kpos < 9; kpos++) {
            int ky = kpos / 3, kx = kpos - ky * 3;
#pragma unroll
            for (int ci = 0; ci < 8; ci++) {
                float v = ins[ci * 324 + (py + ky) * 18 + (px + kx)];
                const float4* wv = (const float4*)(ws + (kpos * 8 + ci) * 96 + cobase);
#pragma unroll
                for (int j4 = 0; j4 < 12; j4++) {
                    float4 wq = wv[j4];
                    acc[j4 * 4 + 0] = fmaf(v, wq.x, acc[j4 * 4 + 0]);
                    acc[j4 * 4 + 1] = fmaf(v, wq.y, acc[j4 * 4 + 1]);
                    acc[j4 * 4 + 2] = fmaf(v, wq.z, acc[j4 * 4 + 2]);
                    acc[j4 * 4 + 3] = fmaf(v, wq.w, acc[j4 * 4 + 3]);
                }
            }
        }
        __syncthreads();
    }
    size_t gp = (size_t)(ty0 + py) * HF + (tx0 + px);
#pragma unroll
    for (int j = 0; j < 48; j++) {
        int co = cobase + j;
        g_feat[gp * FC + co] = fmaxf(fmaf(acc[j], __ldg(sf + co), __ldg(bf + co)), 0.f);
    }
}

// ---------------------------------------------------------------------------
// G[p][0:128] = feat[p] @ W0[0:96,:] + b0.  CTA: 64 pixels, 256 threads
// (pixel x 4 groups of 32 outputs). K chunked by 48.
// ---------------------------------------------------------------------------
__global__ __launch_bounds__(256) void gprep_kernel(const float* __restrict__ w0,
                                                    const float* __restrict__ b0) {
    __shared__ float w0s[48 * 128];
    __shared__ float fs[64 * 49];
    __shared__ float b0s[128];
    int t = threadIdx.x;
    int p0 = blockIdx.x * 64;
    if (t < 128) b0s[t] = b0[t];
    int pix = t & 63, q = t >> 6;
    int jb = q * 32;
    float acc[32];
#pragma unroll
    for (int j = 0; j < 32; j++) acc[j] = 0.f;

    for (int ch = 0; ch < 2; ch++) {
        int ci0 = ch * 48;
        for (int i = t; i < 48 * 128; i += 256) {
            int ci = i >> 7, j = i & 127;
            w0s[i] = w0[(size_t)(ci0 + ci) * 128 + j];
        }
        for (int i = t; i < 64 * 48; i += 256) {
            int pp = i / 48, cc = i - pp * 48;
            fs[pp * 49 + cc] = g_feat[(size_t)(p0 + pp) * FC + ci0 + cc];
        }
        __syncthreads();
        for (int ci = 0; ci < 48; ci++) {
            float v = fs[pix * 49 + ci];
            const float4* wv = (const float4*)(w0s + ci * 128 + jb);
#pragma unroll
            for (int j4 = 0; j4 < 8; j4++) {
                float4 wq = wv[j4];
                acc[j4 * 4 + 0] = fmaf(v, wq.x, acc[j4 * 4 + 0]);
                acc[j4 * 4 + 1] = fmaf(v, wq.y, acc[j4 * 4 + 1]);
                acc[j4 * 4 + 2] = fmaf(v, wq.z, acc[j4 * 4 + 2]);
                acc[j4 * 4 + 3] = fmaf(v, wq.w, acc[j4 * 4 + 3]);
            }
        }
        __syncthreads();
    }
    float4* Gp = (float4*)(g_G + (size_t)(p0 + pix) * UQ + jb);
#pragma unroll
    for (int j4 = 0; j4 < 8; j4++)
        Gp[j4] = make_float4(acc[j4 * 4 + 0] + b0s[jb + j4 * 4 + 0],
                             acc[j4 * 4 + 1] + b0s[jb + j4 * 4 + 1],
                             acc[j4 * 4 + 2] + b0s[jb + j4 * 4 + 2],
                             acc[j4 * 4 + 3] + b0s[jb + j4 * 4 + 3]);
}

// ---------------------------------------------------------------------------
// LIIF query kernel. CTA: 32 queries (8y x 4x tile) * 4 shifts = 128 rows.
// Phase 1: build H0[k][m] = relu(G[p_m][k] + rel_y*W0[96,k] + rel_x*W0[97,k]).
// Phase 2: SGEMM 128x128x128 against W1 (smem-resident), 8x8 reg tile/thread.
// Phase 3: relu(+b1), dot w2 (+b2), local-ensemble blend with swapped areas.
// ---------------------------------------------------------------------------
__device__ __forceinline__ int nearest_i256(float c) {
    float f = (c + 1.0f) * 0.5f * 256.0f - 0.5f;   // ((c+1)*0.5)*256 - 0.5
    int i = (int)rintf(f);                          // round half to even
    return min(max(i, 0), 255);
}

__global__ __launch_bounds__(256) void query_kernel(
        const float* __restrict__ coords, const float* __restrict__ w0,
        const float* __restrict__ w1, const float* __restrict__ b1,
        const float* __restrict__ w2, const float* __restrict__ b2,
        float* __restrict__ out) {
    extern __shared__ float sm[];
    float* W1s   = sm;                // 16384
    float* H0s   = W1s + 16384;       // 16384  [k][m]
    float* w0r0  = H0s + 16384;       // 128
    float* w0r1  = w0r0 + 128;        // 128
    float* b1s   = w0r1 + 128;        // 128
    float* w2s   = b1s + 128;         // 128
    float* relys = w2s + 128;         // 128
    float* relxs = relys + 128;       // 128
    float* preds = relxs + 128;       // 128
    int*   ps    = (int*)(preds + 128);   // 128
    float* red   = (float*)(ps + 128);    // 128*17

    int t = threadIdx.x;
    for (int i = t; i < 16384; i += 256) W1s[i] = w1[i];
    if (t < 128) {
        w0r0[t] = w0[96 * 128 + t];
        w0r1[t] = w0[97 * 128 + t];
        b1s[t]  = b1[t];
        w2s[t]  = w2[t];
    }
    if (t < 32) {
        int qy = blockIdx.y * 8 + (t >> 2);
        int qx = blockIdx.x * 4 + (t & 3);
        int qidx = qy * QRES + qx;
        float y = coords[qidx * 2 + 0];
        float x = coords[qidx * 2 + 1];
        const float SH_M = (float)(-1.0 / 256.0 + 1e-6);
        const float SH_P = (float)( 1.0 / 256.0 + 1e-6);
        const float CLO  = (float)(-1.0 + 1e-6);
        const float CHI  = (float)( 1.0 - 1e-6);
        float cym = fminf(fmaxf(y + SH_M, CLO), CHI);
        float cyp = fminf(fmaxf(y + SH_P, CLO), CHI);
        float cxm = fminf(fmaxf(x + SH_M, CLO), CHI);
        float cxp = fminf(fmaxf(x + SH_P, CLO), CHI);
        int iym = nearest_i256(cym), iyp = nearest_i256(cyp);
        int ixm = nearest_i256(cxm), ixp = nearest_i256(cxp);
        float relym = (y - (((iym + 0.5f) / 256.0f) * 2.0f - 1.0f)) * 256.0f;
        float relyp = (y - (((iyp + 0.5f) / 256.0f) * 2.0f - 1.0f)) * 256.0f;
        float relxm = (x - (((ixm + 0.5f) / 256.0f) * 2.0f - 1.0f)) * 256.0f;
        float relxp = (x - (((ixp + 0.5f) / 256.0f) * 2.0f - 1.0f)) * 256.0f;
        int m0 = t * 4;
        // shift order: (vx,vy) = (-1,-1), (-1,+1), (+1,-1), (+1,+1)
        ps[m0 + 0] = iym * HF + ixm; relys[m0 + 0] = relym; relxs[m0 + 0] = relxm;
        ps[m0 + 1] = iym * HF + ixp; relys[m0 + 1] = relym; relxs[m0 + 1] = relxp;
        ps[m0 + 2] = iyp * HF + ixm; relys[m0 + 2] = relyp; relxs[m0 + 2] = relxm;
        ps[m0 + 3] = iyp * HF + ixp; relys[m0 + 3] = relyp; relxs[m0 + 3] = relxp;
    }
    __syncthreads();

    // ----- phase 1: H0 fill (transposed for GEMM) -----
    {
        int m = t & 127;
        int k0 = (t >> 7) << 6;   // 0 or 64
        int p = ps[m];
        float ry = relys[m], rx = relxs[m];
        const float4* Gr = (const float4*)(g_G + (size_t)p * UQ);
#pragma unroll
        for (int kk = 0; kk < 64; kk += 4) {
            int k = k0 + kk;
            float4 g = Gr[k >> 2];
            float4 a = *(const float4*)(w0r0 + k);
            float4 bb = *(const float4*)(w0r1 + k);
            H0s[(k + 0) * 128 + m] = fmaxf(g.x + ry * a.x + rx * bb.x, 0.f);
            H0s[(k + 1) * 128 + m] = fmaxf(g.y + ry * a.y + rx * bb.y, 0.f);
            H0s[(k + 2) * 128 + m] = fmaxf(g.z + ry * a.z + rx * bb.z, 0.f);
            H0s[(k + 3) * 128 + m] = fmaxf(g.w + ry * a.w + rx * bb.w, 0.f);
        }
    }
    __syncthreads();

    // ----- phase 2: GEMM acc[m][n] += H0[m][k] * W1[k][n] -----
    int tr = t >> 4, tc = t & 15;
    float acc[8][8];
#pragma unroll
    for (int i = 0; i < 8; i++)
#pragma unroll
        for (int j = 0; j < 8; j++) acc[i][j] = 0.f;
    const float* Ab = H0s + tr * 8;
    const float* Bb = W1s + tc * 8;
#pragma unroll 2
    for (int k = 0; k < 128; k++) {
        float4 a0 = *(const float4*)(Ab + k * 128);
        float4 a1 = *(const float4*)(Ab + k * 128 + 4);
        float4 b0v = *(const float4*)(Bb + k * 128);
        float4 b1v = *(const float4*)(Bb + k * 128 + 4);
        float av[8] = {a0.x, a0.y, a0.z, a0.w, a1.x, a1.y, a1.z, a1.w};
        float bv[8] = {b0v.x, b0v.y, b0v.z, b0v.w, b1v.x, b1v.y, b1v.z, b1v.w};
#pragma unroll
        for (int i = 0; i < 8; i++)
#pragma unroll
            for (int j = 0; j < 8; j++)
                acc[i][j] = fmaf(av[i], bv[j], acc[i][j]);
    }

    // ----- phase 3: layer2 + reduction + blend -----
    float b2v = __ldg(b2);
#pragma unroll
    for (int i = 0; i < 8; i++) {
        float sp = 0.f;
#pragma unroll
        for (int j = 0; j < 8; j++) {
            float h = fmaxf(acc[i][j] + b1s[tc * 8 + j], 0.f);
            sp = fmaf(h, w2s[tc * 8 + j], sp);
        }
        red[(tr * 8 + i) * 17 + tc] = sp;
    }
    __syncthreads();
    if (t < 128) {
        float sum = 0.f;
#pragma unroll
        for (int c = 0; c < 16; c++) sum += red[t * 17 + c];
        preds[t] = sum + b2v;
    }
    __syncthreads();
    if (t < 32) {
        int qy = blockIdx.y * 8 + (t >> 2);
        int qx = blockIdx.x * 4 + (t & 3);
        int m0 = t * 4;
        float a0 = fabsf(relys[m0 + 0] * relxs[m0 + 0]) + 1e-9f;
        float a1 = fabsf(relys[m0 + 1] * relxs[m0 + 1]) + 1e-9f;
        float a2 = fabsf(relys[m0 + 2] * relxs[m0 + 2]) + 1e-9f;
        float a3 = fabsf(relys[m0 + 3] * relxs[m0 + 3]) + 1e-9f;
        // areas swapped diagonally: out = (p0*a3 + p1*a2 + p2*a1 + p3*a0)/sum
        float num = preds[m0 + 0] * a3 + preds[m0 + 1] * a2
                  + preds[m0 + 2] * a1 + preds[m0 + 3] * a0;
        out[qy * QRES + qx] = num / (a0 + a1 + a2 + a3);
    }
}

// ---------------------------------------------------------------------------
extern "C" void kernel_launch(void* const* d_in, const int* in_sizes, int n_in,
                              void* d_out, int out_size) {
    const float* feats2  = (const float*)d_in[0];
    const float* feats4  = (const float*)d_in[1];
    const float* feats32 = (const float*)d_in[2];
    const float* coords  = (const float*)d_in[3];
    const float* w2c  = (const float*)d_in[4];
    const float* s2c  = (const float*)d_in[5];
    const float* b2c  = (const float*)d_in[6];
    const float* w4c  = (const float*)d_in[7];
    const float* s4c  = (const float*)d_in[8];
    const float* b4c  = (const float*)d_in[9];
    const float* w32c = (const float*)d_in[10];
    const float* s32c = (const float*)d_in[11];
    const float* b32c = (const float*)d_in[12];
    const float* wf   = (const float*)d_in[13];
    const float* sf   = (const float*)d_in[14];
    const float* bf   = (const float*)d_in[15];
    const float* mw0  = (const float*)d_in[16];
    const float* mb0  = (const float*)d_in[17];
    const float* mw1  = (const float*)d_in[18];
    const float* mb1  = (const float*)d_in[19];
    const float* mw2  = (const float*)d_in[20];
    const float* mb2  = (const float*)d_in[21];
    float* out = (float*)d_out;

    float *catp, *a4p, *a32p;
    cudaGetSymbolAddress((void**)&catp,  g_cat);
    cudaGetSymbolAddress((void**)&a4p,   g_a4);
    cudaGetSymbolAddress((void**)&a32p,  g_a32);

    // ASPP branch convs (a2 writes straight into concat channels 0..31)
    conv1x1_kernel<<<512, 128>>>(feats2,  w2c,  s2c,  b2c,  catp, 256 * 256, 64, 96, 0);
    conv1x1_kernel<<<128, 128>>>(feats4,  w4c,  s4c,  b4c,  a4p, 128 * 128, 128, 32, 0);
    conv1x1_kernel<<<2,   128>>>(feats32, w32c, s32c, b32c, a32p, 16 * 16, 256, 32, 0);

    // bilinear upsample into concat channels 32..95
    upsample_kernel<<<(256 * 256 * 64) / 256, 256>>>();

    // 3x3 fuse conv
    conv3x3_kernel<<<dim3(16, 16), 512>>>(wf, sf, bf);

    // per-pixel G = feat @ W0_feat + b0
    gprep_kernel<<<1024, 256>>>(mw0, mb0);

    // LIIF query + MLP + ensemble
    size_t qsmem = (size_t)(16384 * 2 + 128 * 8 + 128 + 128 * 17) * sizeof(float);
    cudaFuncSetAttribute(query_kernel, cudaFuncAttributeMaxDynamicSharedMemorySize,
                         (int)qsmem);
    query_kernel<<<dim3(128, 64), 256, qsmem>>>(coords, mw0, mw1, mb1, mw2, mb2, out);

    (void)in_sizes; (void)n_in; (void)out_size;
}

// round 3
// speedup vs baseline: 1.4506x; 1.4506x over previous
#include <cuda_runtime.h>
#include <cuda_bf16.h>
#include <math.h>
#include <stdint.h>

// ---------------------------------------------------------------------------
// Decoder: ASPP (3x conv1x1+BN+ReLU, bilinear upsample, conv3x3+BN+ReLU)
// followed by LIIF local-ensemble query with MLP 98->128->128->1.
//
// Round 3: query-stage 128x128x128 GEMM on warp-level mma.sync bf16
// (m16n8k16, sm_80+ ISA -> works on the harness's plain sm_100 target)
// with hi/lo split precision: acc += Ah*Bh + Al*Bh + Ah*Bl  (fp32 accum).
// ---------------------------------------------------------------------------

#define HF 256            // feat grid 256x256
#define FC 96             // fused channels
#define UQ 128            // mlp hidden
#define QRES 512          // query grid
#define LDK 136           // padded row length (elems) for A/B smem tiles

// scratch (device globals; no allocation allowed)
__device__ float g_cat [HF*HF*FC];     // concat(a2, up(a4), up(a32))
__device__ float g_feat[HF*HF*FC];     // after 3x3 conv
__device__ float g_a4  [128*128*32];
__device__ float g_a32 [16*16*32];
__device__ float g_G   [HF*HF*UQ];     // feat @ W0_feat + b0
__device__ __align__(16) __nv_bfloat16 g_w1h[UQ*LDK];  // W1^T hi  [n][k] padded
__device__ __align__(16) __nv_bfloat16 g_w1l[UQ*LDK];  // W1^T lo  [n][k] padded

__device__ __forceinline__ uint32_t smem_u32(const void* p) {
    uint32_t a;
    asm("{ .reg .u64 tmp; cvta.to.shared.u64 tmp, %1; cvt.u32.u64 %0, tmp; }"
        : "=r"(a) : "l"(p));
    return a;
}

#define LDSM4(r, addr) \
    asm volatile("ldmatrix.sync.aligned.m8n8.x4.shared.b16 {%0,%1,%2,%3}, [%4];" \
        : "=r"((r)[0]), "=r"((r)[1]), "=r"((r)[2]), "=r"((r)[3]) : "r"(addr))

#define MMA16816(c, a, b0v, b1v) \
    asm volatile("mma.sync.aligned.m16n8k16.row.col.f32.bf16.bf16.f32 " \
        "{%0,%1,%2,%3}, {%4,%5,%6,%7}, {%8,%9}, {%0,%1,%2,%3};" \
        : "+f"((c)[0]), "+f"((c)[1]), "+f"((c)[2]), "+f"((c)[3]) \
        : "r"((a)[0]), "r"((a)[1]), "r"((a)[2]), "r"((a)[3]), \
          "r"(b0v), "r"(b1v))

// ---------------------------------------------------------------------------
// 1x1 conv + folded BN + ReLU, Cout=32.
// ---------------------------------------------------------------------------
__global__ void conv1x1_kernel(const float* __restrict__ in,
                               const float* __restrict__ w,
                               const float* __restrict__ s,
                               const float* __restrict__ b,
                               float* __restrict__ out,
                               int HW, int Cin, int ostride, int ocoff) {
    __shared__ float wsm[256 * 32];
    __shared__ float ssm[32], bsm[32];
    for (int i = threadIdx.x; i < Cin * 32; i += blockDim.x) wsm[i] = w[i];
    if (threadIdx.x < 32) { ssm[threadIdx.x] = s[threadIdx.x]; bsm[threadIdx.x] = b[threadIdx.x]; }
    __syncthreads();
    int p = blockIdx.x * blockDim.x + threadIdx.x;
    if (p >= HW) return;
    const float* ip = in + (size_t)p * Cin;
    float acc[32];
#pragma unroll
    for (int j = 0; j < 32; j++) acc[j] = 0.f;
    for (int ci = 0; ci < Cin; ci++) {
        float v = __ldg(ip + ci);
        const float* wr = wsm + ci * 32;
#pragma unroll
        for (int j = 0; j < 32; j++) acc[j] = fmaf(v, wr[j], acc[j]);
    }
    float* op = out + (size_t)p * ostride + ocoff;
#pragma unroll
    for (int j = 0; j < 32; j++)
        op[j] = fmaxf(fmaf(acc[j], ssm[j], bsm[j]), 0.f);
}

// ---------------------------------------------------------------------------
// bilinear upsample a4 (128->256) and a32 (16->256) into cat channels 32..95
// ---------------------------------------------------------------------------
__device__ __forceinline__ float bilerp(const float* A, int N, int c,
                                        float sy, float sx) {
    int y0 = (int)floorf(sy); float wy = sy - (float)y0;
    int x0 = (int)floorf(sx); float wx = sx - (float)x0;
    int y0c = max(y0, 0), y1c = min(y0 + 1, N - 1);
    int x0c = max(x0, 0), x1c = min(x0 + 1, N - 1);
    float v00 = A[((size_t)y0c * N + x0c) * 32 + c];
    float v01 = A[((size_t)y0c * N + x1c) * 32 + c];
    float v10 = A[((size_t)y1c * N + x0c) * 32 + c];
    float v11 = A[((size_t)y1c * N + x1c) * 32 + c];
    return (1.f - wy) * ((1.f - wx) * v00 + wx * v01)
         + wy        * ((1.f - wx) * v10 + wx * v11);
}

__global__ void upsample_kernel() {
    int idx = blockIdx.x * blockDim.x + threadIdx.x;
    if (idx >= HF * HF * 64) return;
    int c = idx & 63;
    int p = idx >> 6;
    int oy = p >> 8, ox = p & 255;
    if (c < 32) {
        float sy = (oy + 0.5f) * 0.5f - 0.5f;
        float sx = (ox + 0.5f) * 0.5f - 0.5f;
        g_cat[(size_t)p * FC + 32 + c] = bilerp(g_a4, 128, c, sy, sx);
    } else {
        int cc = c - 32;
        float sy = (oy + 0.5f) * 0.0625f - 0.5f;
        float sx = (ox + 0.5f) * 0.0625f - 0.5f;
        g_cat[(size_t)p * FC + 64 + cc] = bilerp(g_a32, 16, cc, sy, sx);
    }
}

// ---------------------------------------------------------------------------
// 3x3 conv 96->96 + BN + ReLU, SAME padding. (fp32, FFMA)
// ---------------------------------------------------------------------------
__global__ __launch_bounds__(512) void conv3x3_kernel(const float* __restrict__ wf,
                                                      const float* __restrict__ sf,
                                                      const float* __restrict__ bf) {
    __shared__ float ws[9 * 8 * 96];
    __shared__ float ins[8 * 18 * 18];
    int t = threadIdx.x;
    int ty0 = blockIdx.y * 16, tx0 = blockIdx.x * 16;
    int pix = t & 255, half = t >> 8;
    int py = pix >> 4, px = pix & 15;
    int cobase = half * 48;
    float acc[48];
#pragma unroll
    for (int j = 0; j < 48; j++) acc[j] = 0.f;

    for (int ch = 0; ch < 12; ch++) {
        int ci0 = ch * 8;
        for (int i = t; i < 9 * 8 * 96; i += 512) {
            int kpos = i / (8 * 96);
            int r = i - kpos * 8 * 96;
            int ci = r / 96, co = r - ci * 96;
            ws[i] = wf[((size_t)kpos * 96 + ci0 + ci) * 96 + co];
        }
        for (int i = t; i < 8 * 324; i += 512) {
            int ci = i / 324; int r = i - ci * 324;
            int iy = r / 18, ix = r - iy * 18;
            int gy = ty0 + iy - 1, gx = tx0 + ix - 1;
            float v = 0.f;
            if (gy >= 0 && gy < HF && gx >= 0 && gx < HF)
                v = g_cat[((size_t)gy * HF + gx) * FC + ci0 + ci];
            ins[i] = v;
        }
        __syncthreads();
#pragma unroll
        for (int kpos = 0; kpos < 9; kpos++) {
            int ky = kpos / 3, kx = kpos - ky * 3;
#pragma unroll
            for (int ci = 0; ci < 8; ci++) {
                float v = ins[ci * 324 + (py + ky) * 18 + (px + kx)];
                const float4* wv = (const float4*)(ws + (kpos * 8 + ci) * 96 + cobase);
#pragma unroll
                for (int j4 = 0; j4 < 12; j4++) {
                    float4 wq = wv[j4];
                    acc[j4 * 4 + 0] = fmaf(v, wq.x, acc[j4 * 4 + 0]);
                    acc[j4 * 4 + 1] = fmaf(v, wq.y, acc[j4 * 4 + 1]);
                    acc[j4 * 4 + 2] = fmaf(v, wq.z, acc[j4 * 4 + 2]);
                    acc[j4 * 4 + 3] = fmaf(v, wq.w, acc[j4 * 4 + 3]);
                }
            }
        }
        __syncthreads();
    }
    size_t gp = (size_t)(ty0 + py) * HF + (tx0 + px);
#pragma unroll
    for (int j = 0; j < 48; j++) {
        int co = cobase + j;
        g_feat[gp * FC + co] = fmaxf(fmaf(acc[j], __ldg(sf + co), __ldg(bf + co)), 0.f);
    }
}

// ---------------------------------------------------------------------------
// G[p][0:128] = feat[p] @ W0[0:96,:] + b0.
// ---------------------------------------------------------------------------
__global__ __launch_bounds__(256) void gprep_kernel(const float* __restrict__ w0,
                                                    const float* __restrict__ b0) {
    __shared__ float w0s[48 * 128];
    __shared__ float fs[64 * 49];
    __shared__ float b0s[128];
    int t = threadIdx.x;
    int p0 = blockIdx.x * 64;
    if (t < 128) b0s[t] = b0[t];
    int pix = t & 63, q = t >> 6;
    int jb = q * 32;
    float acc[32];
#pragma unroll
    for (int j = 0; j < 32; j++) acc[j] = 0.f;

    for (int ch = 0; ch < 2; ch++) {
        int ci0 = ch * 48;
        for (int i = t; i < 48 * 128; i += 256) {
            int ci = i >> 7, j = i & 127;
            w0s[i] = w0[(size_t)(ci0 + ci) * 128 + j];
        }
        for (int i = t; i < 64 * 48; i += 256) {
            int pp = i / 48, cc = i - pp * 48;
            fs[pp * 49 + cc] = g_feat[(size_t)(p0 + pp) * FC + ci0 + cc];
        }
        __syncthreads();
        for (int ci = 0; ci < 48; ci++) {
            float v = fs[pix * 49 + ci];
            const float4* wv = (const float4*)(w0s + ci * 128 + jb);
#pragma unroll
            for (int j4 = 0; j4 < 8; j4++) {
                float4 wq = wv[j4];
                acc[j4 * 4 + 0] = fmaf(v, wq.x, acc[j4 * 4 + 0]);
                acc[j4 * 4 + 1] = fmaf(v, wq.y, acc[j4 * 4 + 1]);
                acc[j4 * 4 + 2] = fmaf(v, wq.z, acc[j4 * 4 + 2]);
                acc[j4 * 4 + 3] = fmaf(v, wq.w, acc[j4 * 4 + 3]);
            }
        }
        __syncthreads();
    }
    float4* Gp = (float4*)(g_G + (size_t)(p0 + pix) * UQ + jb);
#pragma unroll
    for (int j4 = 0; j4 < 8; j4++)
        Gp[j4] = make_float4(acc[j4 * 4 + 0] + b0s[jb + j4 * 4 + 0],
                             acc[j4 * 4 + 1] + b0s[jb + j4 * 4 + 1],
                             acc[j4 * 4 + 2] + b0s[jb + j4 * 4 + 2],
                             acc[j4 * 4 + 3] + b0s[jb + j4 * 4 + 3]);
}

// ---------------------------------------------------------------------------
// W1 prep: split fp32 W1[k][n] into bf16 hi/lo stored TRANSPOSED [n][k]
// (row-padded to LDK) so query CTAs raw-copy into smem B tiles.
// ---------------------------------------------------------------------------
__global__ void w1prep_kernel(const float* __restrict__ w1) {
    int e = blockIdx.x * 256 + threadIdx.x;   // e = k*128 + n
    int k = e >> 7, n = e & 127;
    float v = w1[e];
    __nv_bfloat16 h = __float2bfloat16(v);
    float lo = v - __bfloat162float(h);
    g_w1h[n * LDK + k] = h;
    g_w1l[n * LDK + k] = __float2bfloat16(lo);
}

// ---------------------------------------------------------------------------
// LIIF query kernel (mma.sync bf16 hi/lo). Each CTA: 8 tiles of 32 queries x
// 4 shifts (M=128 rows), N=128 outputs, K=128.
//   phase 1: H0[m][k] = relu(G[p_m][k] + rel_y*W0[96,k] + rel_x*W0[97,k]),
//            split to bf16 hi/lo into row-major padded smem.
//   phase 2: warp-tiled mma.sync GEMM, 3 accumulating passes.
//   phase 3: relu(+b1), dot w2 (+b2), local-ensemble blend, store.
// ---------------------------------------------------------------------------
__device__ __forceinline__ int nearest_i256(float c) {
    float f = (c + 1.0f) * 0.5f * 256.0f - 0.5f;
    int i = (int)rintf(f);
    return min(max(i, 0), 255);
}

#define OFF_AH   0
#define OFF_AL   34816
#define OFF_BH   69632
#define OFF_BL   104448
#define OFF_MISC 139264
#define QSM_TOTAL (139264 + 1280 * 4)

__global__ __launch_bounds__(256, 1)
void query_mma_kernel(const float* __restrict__ coords,
                      const float* __restrict__ w0,
                      const float* __restrict__ b1,
                      const float* __restrict__ w2,
                      const float* __restrict__ b2,
                      float* __restrict__ out) {
    extern __shared__ __align__(16) char sm[];
    uint32_t base = smem_u32(sm);

    float* miscf = (float*)(sm + OFF_MISC);
    float* w0r0  = miscf;            // 128
    float* w0r1  = miscf + 128;      // 128
    float* b1s   = miscf + 256;      // 128
    float* w2s   = miscf + 384;      // 128
    float* relys = miscf + 512;      // 128
    float* relxs = miscf + 640;      // 128
    float* preds = miscf + 768;      // 128
    float* predp = miscf + 896;      // 256  [row][warp-col]
    int*   ps    = (int*)(miscf + 1152);  // 128

    int t = threadIdx.x;
    int wid = t >> 5, lane = t & 31;

    if (t < 128) {
        w0r0[t] = w0[96 * 128 + t];
        w0r1[t] = w0[97 * 128 + t];
        b1s[t]  = b1[t];
        w2s[t]  = w2[t];
    }
    // copy W1^T hi/lo into smem (linear copy; layout already [n][LDK])
    {
        const uint4* s1 = (const uint4*)g_w1h;
        const uint4* s2 = (const uint4*)g_w1l;
        uint4* d1 = (uint4*)(sm + OFF_BH);
        uint4* d2 = (uint4*)(sm + OFF_BL);
        for (int i = t; i < (UQ * LDK) / 8; i += 256) { d1[i] = s1[i]; d2[i] = s2[i]; }
    }
    float b2v = __ldg(b2);

    // warp tiling: wm 0..3 -> 32 M-rows; wn 0..1 -> 64 N-cols
    int wm = wid & 3, wn = wid >> 2;
    int aro = wm * 32 + (lane & 7) + ((lane >> 3) & 1) * 8;  // + mt*16
    int acol = (lane >> 4) * 8;
    int bro = wn * 64 + (lane & 7) + (lane >> 4) * 8;        // + np*16
    int bcol = ((lane >> 3) & 1) * 8;

    for (int it = 0; it < 8; ++it) {
        int tl = blockIdx.x * 8 + it;
        int qx0 = (tl & 127) * 4, qy0 = (tl >> 7) * 8;

        // ---- meta ----
        if (t < 32) {
            int qy = qy0 + (t >> 2);
            int qx = qx0 + (t & 3);
            int qidx = qy * QRES + qx;
            float y = coords[qidx * 2 + 0];
            float x = coords[qidx * 2 + 1];
            const float SH_M = (float)(-1.0 / 256.0 + 1e-6);
            const float SH_P = (float)( 1.0 / 256.0 + 1e-6);
            const float CLO  = (float)(-1.0 + 1e-6);
            const float CHI  = (float)( 1.0 - 1e-6);
            float cym = fminf(fmaxf(y + SH_M, CLO), CHI);
            float cyp = fminf(fmaxf(y + SH_P, CLO), CHI);
            float cxm = fminf(fmaxf(x + SH_M, CLO), CHI);
            float cxp = fminf(fmaxf(x + SH_P, CLO), CHI);
            int iym = nearest_i256(cym), iyp = nearest_i256(cyp);
            int ixm = nearest_i256(cxm), ixp = nearest_i256(cxp);
            float relym = (y - (((iym + 0.5f) / 256.0f) * 2.0f - 1.0f)) * 256.0f;
            float relyp = (y - (((iyp + 0.5f) / 256.0f) * 2.0f - 1.0f)) * 256.0f;
            float relxm = (x - (((ixm + 0.5f) / 256.0f) * 2.0f - 1.0f)) * 256.0f;
            float relxp = (x - (((ixp + 0.5f) / 256.0f) * 2.0f - 1.0f)) * 256.0f;
            int m0 = t * 4;
            ps[m0 + 0] = iym * HF + ixm; relys[m0 + 0] = relym; relxs[m0 + 0] = relxm;
            ps[m0 + 1] = iym * HF + ixp; relys[m0 + 1] = relym; relxs[m0 + 1] = relxp;
            ps[m0 + 2] = iyp * HF + ixm; relys[m0 + 2] = relyp; relxs[m0 + 2] = relxm;
            ps[m0 + 3] = iyp * HF + ixp; relys[m0 + 3] = relyp; relxs[m0 + 3] = relxp;
        }
        __syncthreads();

        // ---- build A (H0) hi/lo into row-major padded smem ----
        {
            int m = t >> 1, kh = t & 1;
            int p = ps[m];
            float ry = relys[m], rx = relxs[m];
            const float4* Gr = (const float4*)(g_G + (size_t)p * UQ + kh * 64);
            const float4* WA = (const float4*)(w0r0 + kh * 64);
            const float4* WB = (const float4*)(w0r1 + kh * 64);
            char* AH = sm + OFF_AH + (size_t)m * (LDK * 2) + kh * 128;
            char* AL = sm + OFF_AL + (size_t)m * (LDK * 2) + kh * 128;
#pragma unroll
            for (int c = 0; c < 8; c++) {
                float4 g0 = Gr[2 * c], g1 = Gr[2 * c + 1];
                float4 a0 = WA[2 * c], a1 = WA[2 * c + 1];
                float4 q0 = WB[2 * c], q1 = WB[2 * c + 1];
                float v[8];
                v[0] = fmaxf(g0.x + ry * a0.x + rx * q0.x, 0.f);
                v[1] = fmaxf(g0.y + ry * a0.y + rx * q0.y, 0.f);
                v[2] = fmaxf(g0.z + ry * a0.z + rx * q0.z, 0.f);
                v[3] = fmaxf(g0.w + ry * a0.w + rx * q0.w, 0.f);
                v[4] = fmaxf(g1.x + ry * a1.x + rx * q1.x, 0.f);
                v[5] = fmaxf(g1.y + ry * a1.y + rx * q1.y, 0.f);
                v[6] = fmaxf(g1.z + ry * a1.z + rx * q1.z, 0.f);
                v[7] = fmaxf(g1.w + ry * a1.w + rx * q1.w, 0.f);
                uint32_t hv[4], lv[4];
#pragma unroll
                for (int j = 0; j < 4; j++) {
                    float x0 = v[2 * j], x1 = v[2 * j + 1];
                    __nv_bfloat16 h0 = __float2bfloat16(x0);
                    __nv_bfloat16 h1 = __float2bfloat16(x1);
                    float l0 = x0 - __bfloat162float(h0);
                    float l1 = x1 - __bfloat162float(h1);
                    hv[j] = (uint32_t)__bfloat16_as_ushort(h0)
                          | ((uint32_t)__bfloat16_as_ushort(h1) << 16);
                    lv[j] = (uint32_t)__bfloat16_as_ushort(__float2bfloat16(l0))
                          | ((uint32_t)__bfloat16_as_ushort(__float2bfloat16(l1)) << 16);
                }
                *(uint4*)(AH + c * 16) = make_uint4(hv[0], hv[1], hv[2], hv[3]);
                *(uint4*)(AL + c * 16) = make_uint4(lv[0], lv[1], lv[2], lv[3]);
            }
        }
        __syncthreads();

        // ---- GEMM: acc += Ah*Bh + Al*Bh + Ah*Bl ----
        float acc[2][8][4];
#pragma unroll
        for (int i = 0; i < 2; i++)
#pragma unroll
            for (int j = 0; j < 8; j++)
#pragma unroll
                for (int q = 0; q < 4; q++) acc[i][j][q] = 0.f;

#pragma unroll
        for (int k0 = 0; k0 < 128; k0 += 16) {
            uint32_t ah[2][4], al[2][4];
#pragma unroll
            for (int mt = 0; mt < 2; mt++) {
                uint32_t aoff = (uint32_t)((aro + mt * 16) * LDK + k0 + acol) * 2u;
                LDSM4(ah[mt], base + OFF_AH + aoff);
                LDSM4(al[mt], base + OFF_AL + aoff);
            }
#pragma unroll
            for (int np = 0; np < 4; np++) {
                uint32_t boff = (uint32_t)((bro + np * 16) * LDK + k0 + bcol) * 2u;
                uint32_t bh[4], bl[4];
                LDSM4(bh, base + OFF_BH + boff);
                LDSM4(bl, base + OFF_BL + boff);
#pragma unroll
                for (int mt = 0; mt < 2; mt++) {
                    MMA16816(acc[mt][np * 2], ah[mt], bh[0], bh[1]);
                    MMA16816(acc[mt][np * 2], al[mt], bh[0], bh[1]);
                    MMA16816(acc[mt][np * 2], ah[mt], bl[0], bl[1]);
                    MMA16816(acc[mt][np * 2 + 1], ah[mt], bh[2], bh[3]);
                    MMA16816(acc[mt][np * 2 + 1], al[mt], bh[2], bh[3]);
                    MMA16816(acc[mt][np * 2 + 1], ah[mt], bl[2], bl[3]);
                }
            }
        }

        // ---- epilogue: relu(+b1) dot w2, reduce to per-row sums ----
#pragma unroll
        for (int mt = 0; mt < 2; mt++) {
            float pA = 0.f, pB = 0.f;
#pragma unroll
            for (int nt = 0; nt < 8; nt++) {
                int c0 = wn * 64 + nt * 8 + (lane & 3) * 2;
                float ba = b1s[c0], bb = b1s[c0 + 1];
                float wa = w2s[c0], wb = w2s[c0 + 1];
                pA = fmaf(fmaxf(acc[mt][nt][0] + ba, 0.f), wa, pA);
                pA = fmaf(fmaxf(acc[mt][nt][1] + bb, 0.f), wb, pA);
                pB = fmaf(fmaxf(acc[mt][nt][2] + ba, 0.f), wa, pB);
                pB = fmaf(fmaxf(acc[mt][nt][3] + bb, 0.f), wb, pB);
            }
            pA += __shfl_xor_sync(0xFFFFFFFF, pA, 1);
            pA += __shfl_xor_sync(0xFFFFFFFF, pA, 2);
            pB += __shfl_xor_sync(0xFFFFFFFF, pB, 1);
            pB += __shfl_xor_sync(0xFFFFFFFF, pB, 2);
            if ((lane & 3) == 0) {
                int r = wm * 32 + mt * 16 + (lane >> 2);
                predp[r * 2 + wn] = pA;
                predp[(r + 8) * 2 + wn] = pB;
            }
        }
        __syncthreads();
        if (t < 128) preds[t] = predp[2 * t] + predp[2 * t + 1] + b2v;
        __syncthreads();

        // ---- blend (diagonal area swap) ----
        if (t < 32) {
            int qy = qy0 + (t >> 2);
            int qx = qx0 + (t & 3);
            int m0 = t * 4;
            float a0 = fabsf(relys[m0 + 0] * relxs[m0 + 0]) + 1e-9f;
            float a1 = fabsf(relys[m0 + 1] * relxs[m0 + 1]) + 1e-9f;
            float a2 = fabsf(relys[m0 + 2] * relxs[m0 + 2]) + 1e-9f;
            float a3 = fabsf(relys[m0 + 3] * relxs[m0 + 3]) + 1e-9f;
            float num = preds[m0 + 0] * a3 + preds[m0 + 1] * a2
                      + preds[m0 + 2] * a1 + preds[m0 + 3] * a0;
            out[qy * QRES + qx] = num / (a0 + a1 + a2 + a3);
        }
        __syncthreads();
    }
}

// ---------------------------------------------------------------------------
extern "C" void kernel_launch(void* const* d_in, const int* in_sizes, int n_in,
                              void* d_out, int out_size) {
    const float* feats2  = (const float*)d_in[0];
    const float* feats4  = (const float*)d_in[1];
    const float* feats32 = (const float*)d_in[2];
    const float* coords  = (const float*)d_in[3];
    const float* w2c  = (const float*)d_in[4];
    const float* s2c  = (const float*)d_in[5];
    const float* b2c  = (const float*)d_in[6];
    const float* w4c  = (const float*)d_in[7];
    const float* s4c  = (const float*)d_in[8];
    const float* b4c  = (const float*)d_in[9];
    const float* w32c = (const float*)d_in[10];
    const float* s32c = (const float*)d_in[11];
    const float* b32c = (const float*)d_in[12];
    const float* wf   = (const float*)d_in[13];
    const float* sf   = (const float*)d_in[14];
    const float* bf   = (const float*)d_in[15];
    const float* mw0  = (const float*)d_in[16];
    const float* mb0  = (const float*)d_in[17];
    const float* mw1  = (const float*)d_in[18];
    const float* mb1  = (const float*)d_in[19];
    const float* mw2  = (const float*)d_in[20];
    const float* mb2  = (const float*)d_in[21];
    float* out = (float*)d_out;

    float *catp, *a4p, *a32p;
    cudaGetSymbolAddress((void**)&catp,  g_cat);
    cudaGetSymbolAddress((void**)&a4p,   g_a4);
    cudaGetSymbolAddress((void**)&a32p,  g_a32);

    // ASPP branch convs
    conv1x1_kernel<<<512, 128>>>(feats2,  w2c,  s2c,  b2c,  catp, 256 * 256, 64, 96, 0);
    conv1x1_kernel<<<128, 128>>>(feats4,  w4c,  s4c,  b4c,  a4p, 128 * 128, 128, 32, 0);
    conv1x1_kernel<<<2,   128>>>(feats32, w32c, s32c, b32c, a32p, 16 * 16, 256, 32, 0);

    // W1 split-prep (independent of feature path)
    w1prep_kernel<<<64, 256>>>(mw1);

    // bilinear upsample into concat channels 32..95
    upsample_kernel<<<(256 * 256 * 64) / 256, 256>>>();

    // 3x3 fuse conv
    conv3x3_kernel<<<dim3(16, 16), 512>>>(wf, sf, bf);

    // per-pixel G = feat @ W0_feat + b0
    gprep_kernel<<<1024, 256>>>(mw0, mb0);

    // LIIF query + MLP + ensemble (mma.sync)
    cudaFuncSetAttribute(query_mma_kernel, cudaFuncAttributeMaxDynamicSharedMemorySize,
                         QSM_TOTAL);
    query_mma_kernel<<<1024, 256, QSM_TOTAL>>>(coords, mw0, mb1, mw2, mb2, out);

    (void)in_sizes; (void)n_in; (void)out_size;
}

// round 4
// speedup vs baseline: 2.1895x; 1.5094x over previous
#include <cuda_runtime.h>
#include <cuda_bf16.h>
#include <math.h>
#include <stdint.h>

// ---------------------------------------------------------------------------
// Decoder: ASPP (3x conv1x1+BN+ReLU, bilinear upsample, conv3x3+BN+ReLU)
// followed by LIIF local-ensemble query with MLP 98->128->128->1.
//
// Round 4: conv3x3 as implicit GEMM on mma.sync bf16 hi/lo, with the gprep
// GEMM (feat @ W0 + b0) fused into its epilogue. g_feat eliminated.
// ---------------------------------------------------------------------------

#define HF 256            // feat grid 256x256
#define FC 96             // fused channels
#define UQ 128            // mlp hidden
#define QRES 512          // query grid
#define LDK 136           // padded row length (elems) for query A/B smem tiles
#define LDC 104           // padded channel stride for conv tiles (13 words: conflict-free)

// scratch (device globals; no allocation allowed)
__device__ float g_cat [HF*HF*FC];     // concat(a2, up(a4), up(a32))
__device__ float g_a4  [128*128*32];
__device__ float g_a32 [16*16*32];
__device__ float g_G   [HF*HF*UQ];     // feat @ W0_feat + b0
__device__ __align__(16) __nv_bfloat16 g_w1h[UQ*LDK];    // W1^T hi  [n][k]
__device__ __align__(16) __nv_bfloat16 g_w1l[UQ*LDK];    // W1^T lo
__device__ __align__(16) __nv_bfloat16 g_wfh[9*96*LDC];  // conv W [tap][co][ci]
__device__ __align__(16) __nv_bfloat16 g_wfl[9*96*LDC];
__device__ __align__(16) __nv_bfloat16 g_w0h[UQ*LDC];    // W0^T [n][k=ci]
__device__ __align__(16) __nv_bfloat16 g_w0l[UQ*LDC];

__device__ __forceinline__ uint32_t smem_u32(const void* p) {
    uint32_t a;
    asm("{ .reg .u64 tmp; cvta.to.shared.u64 tmp, %1; cvt.u32.u64 %0, tmp; }"
        : "=r"(a) : "l"(p));
    return a;
}

#define LDSM4(r, addr) \
    asm volatile("ldmatrix.sync.aligned.m8n8.x4.shared.b16 {%0,%1,%2,%3}, [%4];" \
        : "=r"((r)[0]), "=r"((r)[1]), "=r"((r)[2]), "=r"((r)[3]) : "r"(addr))

#define MMA16816(c, a, b0v, b1v) \
    asm volatile("mma.sync.aligned.m16n8k16.row.col.f32.bf16.bf16.f32 " \
        "{%0,%1,%2,%3}, {%4,%5,%6,%7}, {%8,%9}, {%0,%1,%2,%3};" \
        : "+f"((c)[0]), "+f"((c)[1]), "+f"((c)[2]), "+f"((c)[3]) \
        : "r"((a)[0]), "r"((a)[1]), "r"((a)[2]), "r"((a)[3]), \
          "r"(b0v), "r"(b1v))

__device__ __forceinline__ uint32_t packbf(float a, float b) {
    return (uint32_t)__bfloat16_as_ushort(__float2bfloat16(a))
         | ((uint32_t)__bfloat16_as_ushort(__float2bfloat16(b)) << 16);
}
__device__ __forceinline__ void split4(float4 v, uint2& h, uint2& l) {
    __nv_bfloat16 h0 = __float2bfloat16(v.x), h1 = __float2bfloat16(v.y);
    __nv_bfloat16 h2 = __float2bfloat16(v.z), h3 = __float2bfloat16(v.w);
    h.x = (uint32_t)__bfloat16_as_ushort(h0) | ((uint32_t)__bfloat16_as_ushort(h1) << 16);
    h.y = (uint32_t)__bfloat16_as_ushort(h2) | ((uint32_t)__bfloat16_as_ushort(h3) << 16);
    l.x = packbf(v.x - __bfloat162float(h0), v.y - __bfloat162float(h1));
    l.y = packbf(v.z - __bfloat162float(h2), v.w - __bfloat162float(h3));
}

// ---------------------------------------------------------------------------
// combined weight prep: wf -> [tap][co][ci] hi/lo, w0 -> [n][ci] hi/lo,
// w1 -> [n][k] hi/lo (all padded, pads zeroed)
// ---------------------------------------------------------------------------
#define WF_N (9*96*LDC)
#define W0_N (UQ*LDC)
#define W1_N (UQ*LDK)
__global__ void prep_kernel(const float* __restrict__ wf,
                            const float* __restrict__ w0,
                            const float* __restrict__ w1) {
    int i = blockIdx.x * 256 + threadIdx.x;
    if (i < WF_N) {
        int tap = i / (96 * LDC);
        int r = i - tap * (96 * LDC);
        int co = r / LDC, ci = r - co * LDC;
        float v = (ci < 96) ? wf[((size_t)tap * 96 + ci) * 96 + co] : 0.f;
        __nv_bfloat16 h = __float2bfloat16(v);
        g_wfh[i] = h; g_wfl[i] = __float2bfloat16(v - __bfloat162float(h));
    } else if (i < WF_N + W0_N) {
        int j = i - WF_N;
        int n = j / LDC, k = j - n * LDC;
        float v = (k < 96) ? w0[(size_t)k * UQ + n] : 0.f;
        __nv_bfloat16 h = __float2bfloat16(v);
        g_w0h[j] = h; g_w0l[j] = __float2bfloat16(v - __bfloat162float(h));
    } else if (i < WF_N + W0_N + W1_N) {
        int j = i - WF_N - W0_N;
        int n = j / LDK, k = j - n * LDK;
        float v = (k < 128) ? w1[(size_t)k * UQ + n] : 0.f;
        __nv_bfloat16 h = __float2bfloat16(v);
        g_w1h[j] = h; g_w1l[j] = __float2bfloat16(v - __bfloat162float(h));
    }
}

// ---------------------------------------------------------------------------
// 1x1 conv + folded BN + ReLU, Cout=32.
// ---------------------------------------------------------------------------
__global__ void conv1x1_kernel(const float* __restrict__ in,
                               const float* __restrict__ w,
                               const float* __restrict__ s,
                               const float* __restrict__ b,
                               float* __restrict__ out,
                               int HW, int Cin, int ostride, int ocoff) {
    __shared__ float wsm[256 * 32];
    __shared__ float ssm[32], bsm[32];
    for (int i = threadIdx.x; i < Cin * 32; i += blockDim.x) wsm[i] = w[i];
    if (threadIdx.x < 32) { ssm[threadIdx.x] = s[threadIdx.x]; bsm[threadIdx.x] = b[threadIdx.x]; }
    __syncthreads();
    int p = blockIdx.x * blockDim.x + threadIdx.x;
    if (p >= HW) return;
    const float* ip = in + (size_t)p * Cin;
    float acc[32];
#pragma unroll
    for (int j = 0; j < 32; j++) acc[j] = 0.f;
    for (int ci = 0; ci < Cin; ci++) {
        float v = __ldg(ip + ci);
        const float* wr = wsm + ci * 32;
#pragma unroll
        for (int j = 0; j < 32; j++) acc[j] = fmaf(v, wr[j], acc[j]);
    }
    float* op = out + (size_t)p * ostride + ocoff;
#pragma unroll
    for (int j = 0; j < 32; j++)
        op[j] = fmaxf(fmaf(acc[j], ssm[j], bsm[j]), 0.f);
}

// ---------------------------------------------------------------------------
// bilinear upsample a4 (128->256) and a32 (16->256) into cat channels 32..95
// ---------------------------------------------------------------------------
__device__ __forceinline__ float bilerp(const float* A, int N, int c,
                                        float sy, float sx) {
    int y0 = (int)floorf(sy); float wy = sy - (float)y0;
    int x0 = (int)floorf(sx); float wx = sx - (float)x0;
    int y0c = max(y0, 0), y1c = min(y0 + 1, N - 1);
    int x0c = max(x0, 0), x1c = min(x0 + 1, N - 1);
    float v00 = A[((size_t)y0c * N + x0c) * 32 + c];
    float v01 = A[((size_t)y0c * N + x1c) * 32 + c];
    float v10 = A[((size_t)y1c * N + x0c) * 32 + c];
    float v11 = A[((size_t)y1c * N + x1c) * 32 + c];
    return (1.f - wy) * ((1.f - wx) * v00 + wx * v01)
         + wy        * ((1.f - wx) * v10 + wx * v11);
}

__global__ void upsample_kernel() {
    int idx = blockIdx.x * blockDim.x + threadIdx.x;
    if (idx >= HF * HF * 64) return;
    int c = idx & 63;
    int p = idx >> 6;
    int oy = p >> 8, ox = p & 255;
    if (c < 32) {
        float sy = (oy + 0.5f) * 0.5f - 0.5f;
        float sx = (ox + 0.5f) * 0.5f - 0.5f;
        g_cat[(size_t)p * FC + 32 + c] = bilerp(g_a4, 128, c, sy, sx);
    } else {
        int cc = c - 32;
        float sy = (oy + 0.5f) * 0.0625f - 0.5f;
        float sx = (ox + 0.5f) * 0.0625f - 0.5f;
        g_cat[(size_t)p * FC + 64 + cc] = bilerp(g_a32, 16, cc, sy, sx);
    }
}

// ---------------------------------------------------------------------------
// Fused conv3x3 (96->96, BN, ReLU) + gprep (feat @ W0 + b0 -> g_G).
// CTA = 16x8 pixel tile (M=128). Implicit GEMM over 9 taps x K=96, bf16
// hi/lo 3-pass mma.sync, fp32 accum. Epilogue converts feat to bf16 hi/lo
// in smem and runs the 128x128x96 W0 GEMM, writing g_G directly.
//
// smem: R1 = halo hi/lo (10*18*LDC bf16 each = 74880 B), reused as feat
//       hi/lo (128*LDC*2 each = 53248 B). R2 = per-tap weights hi/lo
//       (2*19968 B), reused as W0 hi/lo (2*26624 B). misc = sf,bf,b0.
// ---------------------------------------------------------------------------
#define CSM_R1   0
#define CSM_R2   74880
#define CSM_MISC 128128
#define CSM_TOTAL 129408

__global__ __launch_bounds__(256, 1)
void conv3x3g_kernel(const float* __restrict__ sf, const float* __restrict__ bf,
                     const float* __restrict__ b0) {
    extern __shared__ __align__(16) char csm[];
    uint32_t base = smem_u32(csm);
    int t = threadIdx.x, wid = t >> 5, lane = t & 31;
    int px0 = blockIdx.x * 16, py0 = blockIdx.y * 8;

    float* sfs = (float*)(csm + CSM_MISC);   // 96
    float* bfs = sfs + 96;                    // 96
    float* b0s = bfs + 96;                    // 128

    // ---- halo load + hi/lo split (10x18 positions x 96 ch) ----
    for (int i = t; i < 180 * 24; i += 256) {
        int pos = i / 24, c4 = (i - pos * 24) * 4;
        int hy = pos / 18, hx = pos - hy * 18;
        int gy = py0 + hy - 1, gx = px0 + hx - 1;
        float4 v = make_float4(0.f, 0.f, 0.f, 0.f);
        if ((unsigned)gy < 256u && (unsigned)gx < 256u)
            v = *(const float4*)(g_cat + ((size_t)gy * 256 + gx) * FC + c4);
        uint2 hh, ll;
        split4(v, hh, ll);
        *(uint2*)(csm + CSM_R1 + (pos * LDC + c4) * 2) = hh;
        *(uint2*)(csm + CSM_R1 + 37440 + (pos * LDC + c4) * 2) = ll;
    }
    if (t < 96) { sfs[t] = sf[t]; bfs[t] = bf[t]; }
    if (t < 128) b0s[t] = b0[t];

    // warp tiling (conv): wm rows 32, wn (0..1) cols 48
    int wm = wid & 3, wn = wid >> 2;
    int arow0 = wm * 32 + (lane & 7) + ((lane >> 3) & 1) * 8;
    int acol = (lane >> 4) * 8;
    int my0 = arow0 >> 4,        mx0 = arow0 & 15;
    int my1 = (arow0 + 16) >> 4, mx1 = (arow0 + 16) & 15;
    int brow = wn * 48 + (lane & 7) + (lane >> 4) * 8;
    uint32_t boffB = base + CSM_R2 + (uint32_t)(brow * LDC + ((lane >> 3) & 1) * 8) * 2;

    float accc[2][6][4];
#pragma unroll
    for (int i = 0; i < 2; i++)
#pragma unroll
        for (int j = 0; j < 6; j++)
#pragma unroll
            for (int q = 0; q < 4; q++) accc[i][j][q] = 0.f;

    for (int tap = 0; tap < 9; tap++) {
        // stage this tap's weights (hi/lo) into R2
        {
            const uint4* s1 = (const uint4*)(g_wfh + tap * (96 * LDC));
            const uint4* s2 = (const uint4*)(g_wfl + tap * (96 * LDC));
            uint4* d1 = (uint4*)(csm + CSM_R2);
            uint4* d2 = (uint4*)(csm + CSM_R2 + 19968);
            for (int i = t; i < 1248; i += 256) { d1[i] = s1[i]; d2[i] = s2[i]; }
        }
        __syncthreads();

        int ky = tap / 3, kx = tap - ky * 3;
        uint32_t aoff0 = base + CSM_R1
            + (uint32_t)(((my0 + ky) * 18 + mx0 + kx) * LDC + acol) * 2;
        uint32_t aoff1 = base + CSM_R1
            + (uint32_t)(((my1 + ky) * 18 + mx1 + kx) * LDC + acol) * 2;
#pragma unroll
        for (int kc = 0; kc < 6; kc++) {
            uint32_t k2 = kc * 32;
            uint32_t ah[2][4], al[2][4];
            LDSM4(ah[0], aoff0 + k2); LDSM4(al[0], aoff0 + 37440 + k2);
            LDSM4(ah[1], aoff1 + k2); LDSM4(al[1], aoff1 + 37440 + k2);
#pragma unroll
            for (int nb = 0; nb < 3; nb++) {
                uint32_t bo = boffB + nb * (16 * LDC * 2) + k2;
                uint32_t bh[4], bl[4];
                LDSM4(bh, bo); LDSM4(bl, bo + 19968);
#pragma unroll
                for (int mt = 0; mt < 2; mt++) {
                    MMA16816(accc[mt][nb*2],   ah[mt], bh[0], bh[1]);
                    MMA16816(accc[mt][nb*2],   al[mt], bh[0], bh[1]);
                    MMA16816(accc[mt][nb*2],   ah[mt], bl[0], bl[1]);
                    MMA16816(accc[mt][nb*2+1], ah[mt], bh[2], bh[3]);
                    MMA16816(accc[mt][nb*2+1], al[mt], bh[2], bh[3]);
                    MMA16816(accc[mt][nb*2+1], ah[mt], bl[2], bl[3]);
                }
            }
        }
        __syncthreads();
    }

    // ---- conv epilogue: scale/bias/relu -> feat hi/lo into R1; W0 into R2 ----
    {
        const uint4* s1 = (const uint4*)g_w0h;
        const uint4* s2 = (const uint4*)g_w0l;
        uint4* d1 = (uint4*)(csm + CSM_R2);
        uint4* d2 = (uint4*)(csm + CSM_R2 + 26624);
        for (int i = t; i < 1664; i += 256) { d1[i] = s1[i]; d2[i] = s2[i]; }
    }
#pragma unroll
    for (int mt = 0; mt < 2; mt++)
#pragma unroll
        for (int nt = 0; nt < 6; nt++) {
            int r = wm * 32 + mt * 16 + (lane >> 2);
            int c = wn * 48 + nt * 8 + (lane & 3) * 2;
            float s0 = sfs[c], s1v = sfs[c + 1];
            float q0 = bfs[c], q1 = bfs[c + 1];
            float v0 = fmaxf(fmaf(accc[mt][nt][0], s0, q0), 0.f);
            float v1 = fmaxf(fmaf(accc[mt][nt][1], s1v, q1), 0.f);
            float v2 = fmaxf(fmaf(accc[mt][nt][2], s0, q0), 0.f);
            float v3 = fmaxf(fmaf(accc[mt][nt][3], s1v, q1), 0.f);
            __nv_bfloat16 h0 = __float2bfloat16(v0), h1 = __float2bfloat16(v1);
            __nv_bfloat16 h2 = __float2bfloat16(v2), h3 = __float2bfloat16(v3);
            uint32_t o0 = (uint32_t)(r * LDC + c) * 2;
            uint32_t o1 = (uint32_t)((r + 8) * LDC + c) * 2;
            *(uint32_t*)(csm + CSM_R1 + o0) =
                (uint32_t)__bfloat16_as_ushort(h0) | ((uint32_t)__bfloat16_as_ushort(h1) << 16);
            *(uint32_t*)(csm + CSM_R1 + o1) =
                (uint32_t)__bfloat16_as_ushort(h2) | ((uint32_t)__bfloat16_as_ushort(h3) << 16);
            *(uint32_t*)(csm + CSM_R1 + 26624 + o0) =
                packbf(v0 - __bfloat162float(h0), v1 - __bfloat162float(h1));
            *(uint32_t*)(csm + CSM_R1 + 26624 + o1) =
                packbf(v2 - __bfloat162float(h2), v3 - __bfloat162float(h3));
        }
    __syncthreads();

    // ---- gprep GEMM: G[m][n] = feat[m][k] @ W0[k][n], N=128, K=96 ----
    float accg[2][8][4];
#pragma unroll
    for (int i = 0; i < 2; i++)
#pragma unroll
        for (int j = 0; j < 8; j++)
#pragma unroll
            for (int q = 0; q < 4; q++) accg[i][j][q] = 0.f;

    uint32_t gao = base + CSM_R1 + (uint32_t)(arow0 * LDC + acol) * 2;
    int gbrow = wn * 64 + (lane & 7) + (lane >> 4) * 8;
    uint32_t gbo = base + CSM_R2 + (uint32_t)(gbrow * LDC + ((lane >> 3) & 1) * 8) * 2;
#pragma unroll
    for (int kc = 0; kc < 6; kc++) {
        uint32_t k2 = kc * 32;
        uint32_t ah[2][4], al[2][4];
        LDSM4(ah[0], gao + k2);                 LDSM4(al[0], gao + 26624 + k2);
        LDSM4(ah[1], gao + 16 * LDC * 2 + k2);  LDSM4(al[1], gao + 26624 + 16 * LDC * 2 + k2);
#pragma unroll
        for (int np = 0; np < 4; np++) {
            uint32_t bo = gbo + np * (16 * LDC * 2) + k2;
            uint32_t bh[4], bl[4];
            LDSM4(bh, bo); LDSM4(bl, bo + 26624);
#pragma unroll
            for (int mt = 0; mt < 2; mt++) {
                MMA16816(accg[mt][np*2],   ah[mt], bh[0], bh[1]);
                MMA16816(accg[mt][np*2],   al[mt], bh[0], bh[1]);
                MMA16816(accg[mt][np*2],   ah[mt], bl[0], bl[1]);
                MMA16816(accg[mt][np*2+1], ah[mt], bh[2], bh[3]);
                MMA16816(accg[mt][np*2+1], al[mt], bh[2], bh[3]);
                MMA16816(accg[mt][np*2+1], ah[mt], bl[2], bl[3]);
            }
        }
    }

    // ---- write G (+b0) ----
#pragma unroll
    for (int mt = 0; mt < 2; mt++)
#pragma unroll
        for (int nt = 0; nt < 8; nt++) {
            int r = wm * 32 + mt * 16 + (lane >> 2);
            int c = wn * 64 + nt * 8 + (lane & 3) * 2;
            size_t p0 = ((size_t)(py0 + (r >> 4)) * 256 + px0 + (r & 15)) * UQ;
            size_t p1 = ((size_t)(py0 + ((r + 8) >> 4)) * 256 + px0 + ((r + 8) & 15)) * UQ;
            *(float2*)(g_G + p0 + c) =
                make_float2(accg[mt][nt][0] + b0s[c], accg[mt][nt][1] + b0s[c + 1]);
            *(float2*)(g_G + p1 + c) =
                make_float2(accg[mt][nt][2] + b0s[c], accg[mt][nt][3] + b0s[c + 1]);
        }
}

// ---------------------------------------------------------------------------
// LIIF query kernel (mma.sync bf16 hi/lo). Unchanged from Round 3.
// ---------------------------------------------------------------------------
__device__ __forceinline__ int nearest_i256(float c) {
    float f = (c + 1.0f) * 0.5f * 256.0f - 0.5f;
    int i = (int)rintf(f);
    return min(max(i, 0), 255);
}

#define OFF_AH   0
#define OFF_AL   34816
#define OFF_BH   69632
#define OFF_BL   104448
#define OFF_MISC 139264
#define QSM_TOTAL (139264 + 1280 * 4)

__global__ __launch_bounds__(256, 1)
void query_mma_kernel(const float* __restrict__ coords,
                      const float* __restrict__ w0,
                      const float* __restrict__ b1,
                      const float* __restrict__ w2,
                      const float* __restrict__ b2,
                      float* __restrict__ out) {
    extern __shared__ __align__(16) char sm[];
    uint32_t base = smem_u32(sm);

    float* miscf = (float*)(sm + OFF_MISC);
    float* w0r0  = miscf;            // 128
    float* w0r1  = miscf + 128;      // 128
    float* b1s   = miscf + 256;      // 128
    float* w2s   = miscf + 384;      // 128
    float* relys = miscf + 512;      // 128
    float* relxs = miscf + 640;      // 128
    float* preds = miscf + 768;      // 128
    float* predp = miscf + 896;      // 256
    int*   ps    = (int*)(miscf + 1152);  // 128

    int t = threadIdx.x;
    int wid = t >> 5, lane = t & 31;

    if (t < 128) {
        w0r0[t] = w0[96 * 128 + t];
        w0r1[t] = w0[97 * 128 + t];
        b1s[t]  = b1[t];
        w2s[t]  = w2[t];
    }
    {
        const uint4* s1 = (const uint4*)g_w1h;
        const uint4* s2 = (const uint4*)g_w1l;
        uint4* d1 = (uint4*)(sm + OFF_BH);
        uint4* d2 = (uint4*)(sm + OFF_BL);
        for (int i = t; i < (UQ * LDK) / 8; i += 256) { d1[i] = s1[i]; d2[i] = s2[i]; }
    }
    float b2v = __ldg(b2);

    int wm = wid & 3, wn = wid >> 2;
    int aro = wm * 32 + (lane & 7) + ((lane >> 3) & 1) * 8;
    int acol = (lane >> 4) * 8;
    int bro = wn * 64 + (lane & 7) + (lane >> 4) * 8;
    int bcol = ((lane >> 3) & 1) * 8;

    for (int it = 0; it < 8; ++it) {
        int tl = blockIdx.x * 8 + it;
        int qx0 = (tl & 127) * 4, qy0 = (tl >> 7) * 8;

        if (t < 32) {
            int qy = qy0 + (t >> 2);
            int qx = qx0 + (t & 3);
            int qidx = qy * QRES + qx;
            float y = coords[qidx * 2 + 0];
            float x = coords[qidx * 2 + 1];
            const float SH_M = (float)(-1.0 / 256.0 + 1e-6);
            const float SH_P = (float)( 1.0 / 256.0 + 1e-6);
            const float CLO  = (float)(-1.0 + 1e-6);
            const float CHI  = (float)( 1.0 - 1e-6);
            float cym = fminf(fmaxf(y + SH_M, CLO), CHI);
            float cyp = fminf(fmaxf(y + SH_P, CLO), CHI);
            float cxm = fminf(fmaxf(x + SH_M, CLO), CHI);
            float cxp = fminf(fmaxf(x + SH_P, CLO), CHI);
            int iym = nearest_i256(cym), iyp = nearest_i256(cyp);
            int ixm = nearest_i256(cxm), ixp = nearest_i256(cxp);
            float relym = (y - (((iym + 0.5f) / 256.0f) * 2.0f - 1.0f)) * 256.0f;
            float relyp = (y - (((iyp + 0.5f) / 256.0f) * 2.0f - 1.0f)) * 256.0f;
            float relxm = (x - (((ixm + 0.5f) / 256.0f) * 2.0f - 1.0f)) * 256.0f;
            float relxp = (x - (((ixp + 0.5f) / 256.0f) * 2.0f - 1.0f)) * 256.0f;
            int m0 = t * 4;
            ps[m0 + 0] = iym * HF + ixm; relys[m0 + 0] = relym; relxs[m0 + 0] = relxm;
            ps[m0 + 1] = iym * HF + ixp; relys[m0 + 1] = relym; relxs[m0 + 1] = relxp;
            ps[m0 + 2] = iyp * HF + ixm; relys[m0 + 2] = relyp; relxs[m0 + 2] = relxm;
            ps[m0 + 3] = iyp * HF + ixp; relys[m0 + 3] = relyp; relxs[m0 + 3] = relxp;
        }
        __syncthreads();

        {
            int m = t >> 1, kh = t & 1;
            int p = ps[m];
            float ry = relys[m], rx = relxs[m];
            const float4* Gr = (const float4*)(g_G + (size_t)p * UQ + kh * 64);
            const float4* WA = (const float4*)(w0r0 + kh * 64);
            const float4* WB = (const float4*)(w0r1 + kh * 64);
            char* AH = sm + OFF_AH + (size_t)m * (LDK * 2) + kh * 128;
            char* AL = sm + OFF_AL + (size_t)m * (LDK * 2) + kh * 128;
#pragma unroll
            for (int c = 0; c < 8; c++) {
                float4 g0 = Gr[2 * c], g1 = Gr[2 * c + 1];
                float4 a0 = WA[2 * c], a1 = WA[2 * c + 1];
                float4 q0 = WB[2 * c], q1 = WB[2 * c + 1];
                float v[8];
                v[0] = fmaxf(g0.x + ry * a0.x + rx * q0.x, 0.f);
                v[1] = fmaxf(g0.y + ry * a0.y + rx * q0.y, 0.f);
                v[2] = fmaxf(g0.z + ry * a0.z + rx * q0.z, 0.f);
                v[3] = fmaxf(g0.w + ry * a0.w + rx * q0.w, 0.f);
                v[4] = fmaxf(g1.x + ry * a1.x + rx * q1.x, 0.f);
                v[5] = fmaxf(g1.y + ry * a1.y + rx * q1.y, 0.f);
                v[6] = fmaxf(g1.z + ry * a1.z + rx * q1.z, 0.f);
                v[7] = fmaxf(g1.w + ry * a1.w + rx * q1.w, 0.f);
                uint32_t hv[4], lv[4];
#pragma unroll
                for (int j = 0; j < 4; j++) {
                    float x0 = v[2 * j], x1 = v[2 * j + 1];
                    __nv_bfloat16 h0 = __float2bfloat16(x0);
                    __nv_bfloat16 h1 = __float2bfloat16(x1);
                    hv[j] = (uint32_t)__bfloat16_as_ushort(h0)
                          | ((uint32_t)__bfloat16_as_ushort(h1) << 16);
                    lv[j] = packbf(x0 - __bfloat162float(h0), x1 - __bfloat162float(h1));
                }
                *(uint4*)(AH + c * 16) = make_uint4(hv[0], hv[1], hv[2], hv[3]);
                *(uint4*)(AL + c * 16) = make_uint4(lv[0], lv[1], lv[2], lv[3]);
            }
        }
        __syncthreads();

        float acc[2][8][4];
#pragma unroll
        for (int i = 0; i < 2; i++)
#pragma unroll
            for (int j = 0; j < 8; j++)
#pragma unroll
                for (int q = 0; q < 4; q++) acc[i][j][q] = 0.f;

#pragma unroll
        for (int k0 = 0; k0 < 128; k0 += 16) {
            uint32_t ah[2][4], al[2][4];
#pragma unroll
            for (int mt = 0; mt < 2; mt++) {
                uint32_t aoff = (uint32_t)((aro + mt * 16) * LDK + k0 + acol) * 2u;
                LDSM4(ah[mt], base + OFF_AH + aoff);
                LDSM4(al[mt], base + OFF_AL + aoff);
            }
#pragma unroll
            for (int np = 0; np < 4; np++) {
                uint32_t boff = (uint32_t)((bro + np * 16) * LDK + k0 + bcol) * 2u;
                uint32_t bh[4], bl[4];
                LDSM4(bh, base + OFF_BH + boff);
                LDSM4(bl, base + OFF_BL + boff);
#pragma unroll
                for (int mt = 0; mt < 2; mt++) {
                    MMA16816(acc[mt][np * 2], ah[mt], bh[0], bh[1]);
                    MMA16816(acc[mt][np * 2], al[mt], bh[0], bh[1]);
                    MMA16816(acc[mt][np * 2], ah[mt], bl[0], bl[1]);
                    MMA16816(acc[mt][np * 2 + 1], ah[mt], bh[2], bh[3]);
                    MMA16816(acc[mt][np * 2 + 1], al[mt], bh[2], bh[3]);
                    MMA16816(acc[mt][np * 2 + 1], ah[mt], bl[2], bl[3]);
                }
            }
        }

#pragma unroll
        for (int mt = 0; mt < 2; mt++) {
            float pA = 0.f, pB = 0.f;
#pragma unroll
            for (int nt = 0; nt < 8; nt++) {
                int c0 = wn * 64 + nt * 8 + (lane & 3) * 2;
                float ba = b1s[c0], bb = b1s[c0 + 1];
                float wa = w2s[c0], wb = w2s[c0 + 1];
                pA = fmaf(fmaxf(acc[mt][nt][0] + ba, 0.f), wa, pA);
                pA = fmaf(fmaxf(acc[mt][nt][1] + bb, 0.f), wb, pA);
                pB = fmaf(fmaxf(acc[mt][nt][2] + ba, 0.f), wa, pB);
                pB = fmaf(fmaxf(acc[mt][nt][3] + bb, 0.f), wb, pB);
            }
            pA += __shfl_xor_sync(0xFFFFFFFF, pA, 1);
            pA += __shfl_xor_sync(0xFFFFFFFF, pA, 2);
            pB += __shfl_xor_sync(0xFFFFFFFF, pB, 1);
            pB += __shfl_xor_sync(0xFFFFFFFF, pB, 2);
            if ((lane & 3) == 0) {
                int r = wm * 32 + mt * 16 + (lane >> 2);
                predp[r * 2 + wn] = pA;
                predp[(r + 8) * 2 + wn] = pB;
            }
        }
        __syncthreads();
        if (t < 128) preds[t] = predp[2 * t] + predp[2 * t + 1] + b2v;
        __syncthreads();

        if (t < 32) {
            int qy = qy0 + (t >> 2);
            int qx = qx0 + (t & 3);
            int m0 = t * 4;
            float a0 = fabsf(relys[m0 + 0] * relxs[m0 + 0]) + 1e-9f;
            float a1 = fabsf(relys[m0 + 1] * relxs[m0 + 1]) + 1e-9f;
            float a2 = fabsf(relys[m0 + 2] * relxs[m0 + 2]) + 1e-9f;
            float a3 = fabsf(relys[m0 + 3] * relxs[m0 + 3]) + 1e-9f;
            float num = preds[m0 + 0] * a3 + preds[m0 + 1] * a2
                      + preds[m0 + 2] * a1 + preds[m0 + 3] * a0;
            out[qy * QRES + qx] = num / (a0 + a1 + a2 + a3);
        }
        __syncthreads();
    }
}

// ---------------------------------------------------------------------------
extern "C" void kernel_launch(void* const* d_in, const int* in_sizes, int n_in,
                              void* d_out, int out_size) {
    const float* feats2  = (const float*)d_in[0];
    const float* feats4  = (const float*)d_in[1];
    const float* feats32 = (const float*)d_in[2];
    const float* coords  = (const float*)d_in[3];
    const float* w2c  = (const float*)d_in[4];
    const float* s2c  = (const float*)d_in[5];
    const float* b2c  = (const float*)d_in[6];
    const float* w4c  = (const float*)d_in[7];
    const float* s4c  = (const float*)d_in[8];
    const float* b4c  = (const float*)d_in[9];
    const float* w32c = (const float*)d_in[10];
    const float* s32c = (const float*)d_in[11];
    const float* b32c = (const float*)d_in[12];
    const float* wf   = (const float*)d_in[13];
    const float* sf   = (const float*)d_in[14];
    const float* bf   = (const float*)d_in[15];
    const float* mw0  = (const float*)d_in[16];
    const float* mb0  = (const float*)d_in[17];
    const float* mw1  = (const float*)d_in[18];
    const float* mb1  = (const float*)d_in[19];
    const float* mw2  = (const float*)d_in[20];
    const float* mb2  = (const float*)d_in[21];
    float* out = (float*)d_out;

    float *catp, *a4p, *a32p;
    cudaGetSymbolAddress((void**)&catp,  g_cat);
    cudaGetSymbolAddress((void**)&a4p,   g_a4);
    cudaGetSymbolAddress((void**)&a32p,  g_a32);

    // launch order chosen so ncu (-s 5 -c 1) captures conv3x3g_kernel (idx 5)
    prep_kernel<<<(WF_N + W0_N + W1_N + 255) / 256, 256>>>(wf, mw0, mw1);   // 0
    conv1x1_kernel<<<128, 128>>>(feats4,  w4c,  s4c,  b4c,  a4p, 128 * 128, 128, 32, 0);  // 1
    conv1x1_kernel<<<2,   128>>>(feats32, w32c, s32c, b32c, a32p, 16 * 16, 256, 32, 0);   // 2
    upsample_kernel<<<(256 * 256 * 64) / 256, 256>>>();                     // 3
    conv1x1_kernel<<<512, 128>>>(feats2,  w2c,  s2c,  b2c,  catp, 256 * 256, 64, 96, 0);  // 4

    cudaFuncSetAttribute(conv3x3g_kernel, cudaFuncAttributeMaxDynamicSharedMemorySize,
                         CSM_TOTAL);
    conv3x3g_kernel<<<dim3(16, 32), 256, CSM_TOTAL>>>(sf, bf, mb0);         // 5

    cudaFuncSetAttribute(query_mma_kernel, cudaFuncAttributeMaxDynamicSharedMemorySize,
                         QSM_TOTAL);
    query_mma_kernel<<<1024, 256, QSM_TOTAL>>>(coords, mw0, mb1, mw2, mb2, out);  // 6

    (void)in_sizes; (void)n_in; (void)out_size;
}

// round 5
// speedup vs baseline: 2.6539x; 1.2121x over previous
#include <cuda_runtime.h>
#include <cuda_bf16.h>
#include <cuda_fp16.h>
#include <math.h>
#include <stdint.h>

// ---------------------------------------------------------------------------
// Decoder: ASPP (3x conv1x1+BN+ReLU, bilinear upsample, conv3x3+BN+ReLU)
// followed by LIIF local-ensemble query with MLP 98->128->128->1.
//
// Round 5: fp16 2-pass split GEMMs (activations hi/lo, weights single fp16)
// on mma.sync m16n8k16 -> 2/3 the MMA count of the bf16 3-pass scheme, and
// smaller smem enabling 2 CTAs/SM on both big kernels.
// ---------------------------------------------------------------------------

#define HF 256            // feat grid 256x256
#define FC 96             // fused channels
#define UQ 128            // mlp hidden
#define QRES 512          // query grid
#define LDK 136           // padded row length (elems) for query A/B smem tiles
#define LDC 104           // padded channel stride for conv tiles (13 words: conflict-free)

// scratch (device globals; no allocation allowed)
__device__ float g_cat [HF*HF*FC];     // concat(a2, up(a4), up(a32))
__device__ float g_a4  [128*128*32];
__device__ float g_a32 [16*16*32];
__device__ float g_G   [HF*HF*UQ];     // feat @ W0_feat + b0
__device__ __align__(16) __half g_w1[UQ*LDK];    // W1^T fp16 [n][k]
__device__ __align__(16) __half g_wf[9*96*LDC];  // conv W fp16 [tap][co][ci]
__device__ __align__(16) __half g_w0[UQ*LDC];    // W0^T fp16 [n][k=ci]

__device__ __forceinline__ uint32_t smem_u32(const void* p) {
    uint32_t a;
    asm("{ .reg .u64 tmp; cvta.to.shared.u64 tmp, %1; cvt.u32.u64 %0, tmp; }"
        : "=r"(a) : "l"(p));
    return a;
}

#define LDSM4(r, addr) \
    asm volatile("ldmatrix.sync.aligned.m8n8.x4.shared.b16 {%0,%1,%2,%3}, [%4];" \
        : "=r"((r)[0]), "=r"((r)[1]), "=r"((r)[2]), "=r"((r)[3]) : "r"(addr))

#define MMA16816(c, a, b0v, b1v) \
    asm volatile("mma.sync.aligned.m16n8k16.row.col.f32.f16.f16.f32 " \
        "{%0,%1,%2,%3}, {%4,%5,%6,%7}, {%8,%9}, {%0,%1,%2,%3};" \
        : "+f"((c)[0]), "+f"((c)[1]), "+f"((c)[2]), "+f"((c)[3]) \
        : "r"((a)[0]), "r"((a)[1]), "r"((a)[2]), "r"((a)[3]), \
          "r"(b0v), "r"(b1v))

__device__ __forceinline__ uint32_t packh(float a, float b) {
    __half2 h = __floats2half2_rn(a, b);
    return *(uint32_t*)&h;
}
__device__ __forceinline__ void splith4(float4 v, uint2& h, uint2& l) {
    __half h0 = __float2half_rn(v.x), h1 = __float2half_rn(v.y);
    __half h2 = __float2half_rn(v.z), h3 = __float2half_rn(v.w);
    h.x = (uint32_t)__half_as_ushort(h0) | ((uint32_t)__half_as_ushort(h1) << 16);
    h.y = (uint32_t)__half_as_ushort(h2) | ((uint32_t)__half_as_ushort(h3) << 16);
    l.x = packh(v.x - __half2float(h0), v.y - __half2float(h1));
    l.y = packh(v.z - __half2float(h2), v.w - __half2float(h3));
}

// ---------------------------------------------------------------------------
// weight prep: wf -> [tap][co][ci] fp16, w0 -> [n][ci] fp16, w1 -> [n][k] fp16
// ---------------------------------------------------------------------------
#define WF_N (9*96*LDC)
#define W0_N (UQ*LDC)
#define W1_N (UQ*LDK)
__global__ void prep_kernel(const float* __restrict__ wf,
                            const float* __restrict__ w0,
                            const float* __restrict__ w1) {
    int i = blockIdx.x * 256 + threadIdx.x;
    if (i < WF_N) {
        int tap = i / (96 * LDC);
        int r = i - tap * (96 * LDC);
        int co = r / LDC, ci = r - co * LDC;
        float v = (ci < 96) ? wf[((size_t)tap * 96 + ci) * 96 + co] : 0.f;
        g_wf[i] = __float2half_rn(v);
    } else if (i < WF_N + W0_N) {
        int j = i - WF_N;
        int n = j / LDC, k = j - n * LDC;
        float v = (k < 96) ? w0[(size_t)k * UQ + n] : 0.f;
        g_w0[j] = __float2half_rn(v);
    } else if (i < WF_N + W0_N + W1_N) {
        int j = i - WF_N - W0_N;
        int n = j / LDK, k = j - n * LDK;
        float v = (k < 128) ? w1[(size_t)k * UQ + n] : 0.f;
        g_w1[j] = __float2half_rn(v);
    }
}

// ---------------------------------------------------------------------------
// 1x1 conv + folded BN + ReLU, Cout=32.
// ---------------------------------------------------------------------------
__global__ void conv1x1_kernel(const float* __restrict__ in,
                               const float* __restrict__ w,
                               const float* __restrict__ s,
                               const float* __restrict__ b,
                               float* __restrict__ out,
                               int HW, int Cin, int ostride, int ocoff) {
    __shared__ float wsm[256 * 32];
    __shared__ float ssm[32], bsm[32];
    for (int i = threadIdx.x; i < Cin * 32; i += blockDim.x) wsm[i] = w[i];
    if (threadIdx.x < 32) { ssm[threadIdx.x] = s[threadIdx.x]; bsm[threadIdx.x] = b[threadIdx.x]; }
    __syncthreads();
    int p = blockIdx.x * blockDim.x + threadIdx.x;
    if (p >= HW) return;
    const float* ip = in + (size_t)p * Cin;
    float acc[32];
#pragma unroll
    for (int j = 0; j < 32; j++) acc[j] = 0.f;
    for (int ci = 0; ci < Cin; ci++) {
        float v = __ldg(ip + ci);
        const float* wr = wsm + ci * 32;
#pragma unroll
        for (int j = 0; j < 32; j++) acc[j] = fmaf(v, wr[j], acc[j]);
    }
    float* op = out + (size_t)p * ostride + ocoff;
#pragma unroll
    for (int j = 0; j < 32; j++)
        op[j] = fmaxf(fmaf(acc[j], ssm[j], bsm[j]), 0.f);
}

// ---------------------------------------------------------------------------
// bilinear upsample a4 (128->256) and a32 (16->256) into cat channels 32..95
// ---------------------------------------------------------------------------
__device__ __forceinline__ float bilerp(const float* A, int N, int c,
                                        float sy, float sx) {
    int y0 = (int)floorf(sy); float wy = sy - (float)y0;
    int x0 = (int)floorf(sx); float wx = sx - (float)x0;
    int y0c = max(y0, 0), y1c = min(y0 + 1, N - 1);
    int x0c = max(x0, 0), x1c = min(x0 + 1, N - 1);
    float v00 = A[((size_t)y0c * N + x0c) * 32 + c];
    float v01 = A[((size_t)y0c * N + x1c) * 32 + c];
    float v10 = A[((size_t)y1c * N + x0c) * 32 + c];
    float v11 = A[((size_t)y1c * N + x1c) * 32 + c];
    return (1.f - wy) * ((1.f - wx) * v00 + wx * v01)
         + wy        * ((1.f - wx) * v10 + wx * v11);
}

__global__ void upsample_kernel() {
    int idx = blockIdx.x * blockDim.x + threadIdx.x;
    if (idx >= HF * HF * 64) return;
    int c = idx & 63;
    int p = idx >> 6;
    int oy = p >> 8, ox = p & 255;
    if (c < 32) {
        float sy = (oy + 0.5f) * 0.5f - 0.5f;
        float sx = (ox + 0.5f) * 0.5f - 0.5f;
        g_cat[(size_t)p * FC + 32 + c] = bilerp(g_a4, 128, c, sy, sx);
    } else {
        int cc = c - 32;
        float sy = (oy + 0.5f) * 0.0625f - 0.5f;
        float sx = (ox + 0.5f) * 0.0625f - 0.5f;
        g_cat[(size_t)p * FC + 64 + cc] = bilerp(g_a32, 16, cc, sy, sx);
    }
}

// ---------------------------------------------------------------------------
// Fused conv3x3 (96->96, BN, ReLU) + gprep (feat @ W0 + b0 -> g_G).
// CTA = 16x8 pixel tile (M=128). fp16 2-pass: pixels hi/lo, weights single.
// smem: R1 halo hi/lo (2x37440B), reused as feat hi/lo (2x26624B).
//       R2 tap weights (19968B) / W0 (26624B). misc = sf,bf,b0.
// ---------------------------------------------------------------------------
#define CSM_R1   0
#define CSM_R2   74880
#define CSM_MISC 101504
#define CSM_TOTAL (101504 + 1280)

__global__ __launch_bounds__(256, 2)
void conv3x3g_kernel(const float* __restrict__ sf, const float* __restrict__ bf,
                     const float* __restrict__ b0) {
    extern __shared__ __align__(16) char csm[];
    uint32_t base = smem_u32(csm);
    int t = threadIdx.x, wid = t >> 5, lane = t & 31;
    int px0 = blockIdx.x * 16, py0 = blockIdx.y * 8;

    float* sfs = (float*)(csm + CSM_MISC);   // 96
    float* bfs = sfs + 96;                    // 96
    float* b0s = bfs + 96;                    // 128

    // ---- halo load + fp16 hi/lo split (10x18 positions x 96 ch) ----
    for (int i = t; i < 180 * 24; i += 256) {
        int pos = i / 24, c4 = (i - pos * 24) * 4;
        int hy = pos / 18, hx = pos - hy * 18;
        int gy = py0 + hy - 1, gx = px0 + hx - 1;
        float4 v = make_float4(0.f, 0.f, 0.f, 0.f);
        if ((unsigned)gy < 256u && (unsigned)gx < 256u)
            v = *(const float4*)(g_cat + ((size_t)gy * 256 + gx) * FC + c4);
        uint2 hh, ll;
        splith4(v, hh, ll);
        *(uint2*)(csm + CSM_R1 + (pos * LDC + c4) * 2) = hh;
        *(uint2*)(csm + CSM_R1 + 37440 + (pos * LDC + c4) * 2) = ll;
    }
    if (t < 96) { sfs[t] = sf[t]; bfs[t] = bf[t]; }
    if (t < 128) b0s[t] = b0[t];

    // warp tiling (conv): wm rows 32, wn (0..1) cols 48
    int wm = wid & 3, wn = wid >> 2;
    int arow0 = wm * 32 + (lane & 7) + ((lane >> 3) & 1) * 8;
    int acol = (lane >> 4) * 8;
    int my0 = arow0 >> 4,        mx0 = arow0 & 15;
    int my1 = (arow0 + 16) >> 4, mx1 = (arow0 + 16) & 15;
    int brow = wn * 48 + (lane & 7) + (lane >> 4) * 8;
    uint32_t boffB = base + CSM_R2 + (uint32_t)(brow * LDC + ((lane >> 3) & 1) * 8) * 2;

    float accc[2][6][4];
#pragma unroll
    for (int i = 0; i < 2; i++)
#pragma unroll
        for (int j = 0; j < 6; j++)
#pragma unroll
            for (int q = 0; q < 4; q++) accc[i][j][q] = 0.f;

    for (int tap = 0; tap < 9; tap++) {
        // stage this tap's weights into R2
        {
            const uint4* s1 = (const uint4*)(g_wf + tap * (96 * LDC));
            uint4* d1 = (uint4*)(csm + CSM_R2);
            for (int i = t; i < 1248; i += 256) d1[i] = s1[i];
        }
        __syncthreads();

        int ky = tap / 3, kx = tap - ky * 3;
        uint32_t aoff0 = base + CSM_R1
            + (uint32_t)(((my0 + ky) * 18 + mx0 + kx) * LDC + acol) * 2;
        uint32_t aoff1 = base + CSM_R1
            + (uint32_t)(((my1 + ky) * 18 + mx1 + kx) * LDC + acol) * 2;
#pragma unroll
        for (int kc = 0; kc < 6; kc++) {
            uint32_t k2 = kc * 32;
            uint32_t ah[2][4], al[2][4];
            LDSM4(ah[0], aoff0 + k2); LDSM4(al[0], aoff0 + 37440 + k2);
            LDSM4(ah[1], aoff1 + k2); LDSM4(al[1], aoff1 + 37440 + k2);
#pragma unroll
            for (int nb = 0; nb < 3; nb++) {
                uint32_t bo = boffB + nb * (16 * LDC * 2) + k2;
                uint32_t bh[4];
                LDSM4(bh, bo);
#pragma unroll
                for (int mt = 0; mt < 2; mt++) {
                    MMA16816(accc[mt][nb*2],   ah[mt], bh[0], bh[1]);
                    MMA16816(accc[mt][nb*2],   al[mt], bh[0], bh[1]);
                    MMA16816(accc[mt][nb*2+1], ah[mt], bh[2], bh[3]);
                    MMA16816(accc[mt][nb*2+1], al[mt], bh[2], bh[3]);
                }
            }
        }
        __syncthreads();
    }

    // ---- conv epilogue: scale/bias/relu -> feat hi/lo into R1; W0 into R2 ----
    {
        const uint4* s1 = (const uint4*)g_w0;
        uint4* d1 = (uint4*)(csm + CSM_R2);
        for (int i = t; i < 1664; i += 256) d1[i] = s1[i];
    }
#pragma unroll
    for (int mt = 0; mt < 2; mt++)
#pragma unroll
        for (int nt = 0; nt < 6; nt++) {
            int r = wm * 32 + mt * 16 + (lane >> 2);
            int c = wn * 48 + nt * 8 + (lane & 3) * 2;
            float s0 = sfs[c], s1v = sfs[c + 1];
            float q0 = bfs[c], q1 = bfs[c + 1];
            float v0 = fmaxf(fmaf(accc[mt][nt][0], s0, q0), 0.f);
            float v1 = fmaxf(fmaf(accc[mt][nt][1], s1v, q1), 0.f);
            float v2 = fmaxf(fmaf(accc[mt][nt][2], s0, q0), 0.f);
            float v3 = fmaxf(fmaf(accc[mt][nt][3], s1v, q1), 0.f);
            __half h0 = __float2half_rn(v0), h1 = __float2half_rn(v1);
            __half h2 = __float2half_rn(v2), h3 = __float2half_rn(v3);
            uint32_t o0 = (uint32_t)(r * LDC + c) * 2;
            uint32_t o1 = (uint32_t)((r + 8) * LDC + c) * 2;
            *(uint32_t*)(csm + CSM_R1 + o0) =
                (uint32_t)__half_as_ushort(h0) | ((uint32_t)__half_as_ushort(h1) << 16);
            *(uint32_t*)(csm + CSM_R1 + o1) =
                (uint32_t)__half_as_ushort(h2) | ((uint32_t)__half_as_ushort(h3) << 16);
            *(uint32_t*)(csm + CSM_R1 + 26624 + o0) =
                packh(v0 - __half2float(h0), v1 - __half2float(h1));
            *(uint32_t*)(csm + CSM_R1 + 26624 + o1) =
                packh(v2 - __half2float(h2), v3 - __half2float(h3));
        }
    __syncthreads();

    // ---- gprep GEMM: G[m][n] = feat[m][k] @ W0[k][n], N=128, K=96 ----
    float accg[2][8][4];
#pragma unroll
    for (int i = 0; i < 2; i++)
#pragma unroll
        for (int j = 0; j < 8; j++)
#pragma unroll
            for (int q = 0; q < 4; q++) accg[i][j][q] = 0.f;

    uint32_t gao = base + CSM_R1 + (uint32_t)(arow0 * LDC + acol) * 2;
    int gbrow = wn * 64 + (lane & 7) + (lane >> 4) * 8;
    uint32_t gbo = base + CSM_R2 + (uint32_t)(gbrow * LDC + ((lane >> 3) & 1) * 8) * 2;
#pragma unroll
    for (int kc = 0; kc < 6; kc++) {
        uint32_t k2 = kc * 32;
        uint32_t ah[2][4], al[2][4];
        LDSM4(ah[0], gao + k2);                 LDSM4(al[0], gao + 26624 + k2);
        LDSM4(ah[1], gao + 16 * LDC * 2 + k2);  LDSM4(al[1], gao + 26624 + 16 * LDC * 2 + k2);
#pragma unroll
        for (int np = 0; np < 4; np++) {
            uint32_t bo = gbo + np * (16 * LDC * 2) + k2;
            uint32_t bh[4];
            LDSM4(bh, bo);
#pragma unroll
            for (int mt = 0; mt < 2; mt++) {
                MMA16816(accg[mt][np*2],   ah[mt], bh[0], bh[1]);
                MMA16816(accg[mt][np*2],   al[mt], bh[0], bh[1]);
                MMA16816(accg[mt][np*2+1], ah[mt], bh[2], bh[3]);
                MMA16816(accg[mt][np*2+1], al[mt], bh[2], bh[3]);
            }
        }
    }

    // ---- write G (+b0) ----
#pragma unroll
    for (int mt = 0; mt < 2; mt++)
#pragma unroll
        for (int nt = 0; nt < 8; nt++) {
            int r = wm * 32 + mt * 16 + (lane >> 2);
            int c = wn * 64 + nt * 8 + (lane & 3) * 2;
            size_t p0 = ((size_t)(py0 + (r >> 4)) * 256 + px0 + (r & 15)) * UQ;
            size_t p1 = ((size_t)(py0 + ((r + 8) >> 4)) * 256 + px0 + ((r + 8) & 15)) * UQ;
            *(float2*)(g_G + p0 + c) =
                make_float2(accg[mt][nt][0] + b0s[c], accg[mt][nt][1] + b0s[c + 1]);
            *(float2*)(g_G + p1 + c) =
                make_float2(accg[mt][nt][2] + b0s[c], accg[mt][nt][3] + b0s[c + 1]);
        }
}

// ---------------------------------------------------------------------------
// LIIF query kernel (mma.sync fp16 2-pass). 8 tiles/CTA of 32 queries x 4
// shifts (M=128), N=128, K=128.
// ---------------------------------------------------------------------------
__device__ __forceinline__ int nearest_i256(float c) {
    float f = (c + 1.0f) * 0.5f * 256.0f - 0.5f;
    int i = (int)rintf(f);
    return min(max(i, 0), 255);
}

#define OFF_AH   0
#define OFF_AL   34816
#define OFF_B    69632
#define OFF_MISC 104448
#define QSM_TOTAL (104448 + 1280 * 4)

__global__ __launch_bounds__(256, 2)
void query_mma_kernel(const float* __restrict__ coords,
                      const float* __restrict__ w0,
                      const float* __restrict__ b1,
                      const float* __restrict__ w2,
                      const float* __restrict__ b2,
                      float* __restrict__ out) {
    extern __shared__ __align__(16) char sm[];
    uint32_t base = smem_u32(sm);

    float* miscf = (float*)(sm + OFF_MISC);
    float* w0r0  = miscf;            // 128
    float* w0r1  = miscf + 128;      // 128
    float* b1s   = miscf + 256;      // 128
    float* w2s   = miscf + 384;      // 128
    float* relys = miscf + 512;      // 128
    float* relxs = miscf + 640;      // 128
    float* preds = miscf + 768;      // 128
    float* predp = miscf + 896;      // 256
    int*   ps    = (int*)(miscf + 1152);  // 128

    int t = threadIdx.x;
    int wid = t >> 5, lane = t & 31;

    if (t < 128) {
        w0r0[t] = w0[96 * 128 + t];
        w0r1[t] = w0[97 * 128 + t];
        b1s[t]  = b1[t];
        w2s[t]  = w2[t];
    }
    {
        const uint4* s1 = (const uint4*)g_w1;
        uint4* d1 = (uint4*)(sm + OFF_B);
        for (int i = t; i < (UQ * LDK) / 8; i += 256) d1[i] = s1[i];
    }
    float b2v = __ldg(b2);

    int wm = wid & 3, wn = wid >> 2;
    int aro = wm * 32 + (lane & 7) + ((lane >> 3) & 1) * 8;
    int acol = (lane >> 4) * 8;
    int bro = wn * 64 + (lane & 7) + (lane >> 4) * 8;
    int bcol = ((lane >> 3) & 1) * 8;

    for (int it = 0; it < 8; ++it) {
        int tl = blockIdx.x * 8 + it;
        int qx0 = (tl & 127) * 4, qy0 = (tl >> 7) * 8;

        if (t < 32) {
            int qy = qy0 + (t >> 2);
            int qx = qx0 + (t & 3);
            int qidx = qy * QRES + qx;
            float y = coords[qidx * 2 + 0];
            float x = coords[qidx * 2 + 1];
            const float SH_M = (float)(-1.0 / 256.0 + 1e-6);
            const float SH_P = (float)( 1.0 / 256.0 + 1e-6);
            const float CLO  = (float)(-1.0 + 1e-6);
            const float CHI  = (float)( 1.0 - 1e-6);
            float cym = fminf(fmaxf(y + SH_M, CLO), CHI);
            float cyp = fminf(fmaxf(y + SH_P, CLO), CHI);
            float cxm = fminf(fmaxf(x + SH_M, CLO), CHI);
            float cxp = fminf(fmaxf(x + SH_P, CLO), CHI);
            int iym = nearest_i256(cym), iyp = nearest_i256(cyp);
            int ixm = nearest_i256(cxm), ixp = nearest_i256(cxp);
            float relym = (y - (((iym + 0.5f) / 256.0f) * 2.0f - 1.0f)) * 256.0f;
            float relyp = (y - (((iyp + 0.5f) / 256.0f) * 2.0f - 1.0f)) * 256.0f;
            float relxm = (x - (((ixm + 0.5f) / 256.0f) * 2.0f - 1.0f)) * 256.0f;
            float relxp = (x - (((ixp + 0.5f) / 256.0f) * 2.0f - 1.0f)) * 256.0f;
            int m0 = t * 4;
            ps[m0 + 0] = iym * HF + ixm; relys[m0 + 0] = relym; relxs[m0 + 0] = relxm;
            ps[m0 + 1] = iym * HF + ixp; relys[m0 + 1] = relym; relxs[m0 + 1] = relxp;
            ps[m0 + 2] = iyp * HF + ixm; relys[m0 + 2] = relyp; relxs[m0 + 2] = relxm;
            ps[m0 + 3] = iyp * HF + ixp; relys[m0 + 3] = relyp; relxs[m0 + 3] = relxp;
        }
        __syncthreads();

        // ---- build A (H0) fp16 hi/lo ----
        {
            int m = t >> 1, kh = t & 1;
            int p = ps[m];
            float ry = relys[m], rx = relxs[m];
            const float4* Gr = (const float4*)(g_G + (size_t)p * UQ + kh * 64);
            const float4* WA = (const float4*)(w0r0 + kh * 64);
            const float4* WB = (const float4*)(w0r1 + kh * 64);
            char* AH = sm + OFF_AH + (size_t)m * (LDK * 2) + kh * 128;
            char* AL = sm + OFF_AL + (size_t)m * (LDK * 2) + kh * 128;
#pragma unroll
            for (int c = 0; c < 8; c++) {
                float4 g0 = Gr[2 * c], g1 = Gr[2 * c + 1];
                float4 a0 = WA[2 * c], a1 = WA[2 * c + 1];
                float4 q0 = WB[2 * c], q1 = WB[2 * c + 1];
                float v[8];
                v[0] = fmaxf(g0.x + ry * a0.x + rx * q0.x, 0.f);
                v[1] = fmaxf(g0.y + ry * a0.y + rx * q0.y, 0.f);
                v[2] = fmaxf(g0.z + ry * a0.z + rx * q0.z, 0.f);
                v[3] = fmaxf(g0.w + ry * a0.w + rx * q0.w, 0.f);
                v[4] = fmaxf(g1.x + ry * a1.x + rx * q1.x, 0.f);
                v[5] = fmaxf(g1.y + ry * a1.y + rx * q1.y, 0.f);
                v[6] = fmaxf(g1.z + ry * a1.z + rx * q1.z, 0.f);
                v[7] = fmaxf(g1.w + ry * a1.w + rx * q1.w, 0.f);
                uint32_t hv[4], lv[4];
#pragma unroll
                for (int j = 0; j < 4; j++) {
                    float x0 = v[2 * j], x1 = v[2 * j + 1];
                    __half h0 = __float2half_rn(x0);
                    __half h1 = __float2half_rn(x1);
                    hv[j] = (uint32_t)__half_as_ushort(h0)
                          | ((uint32_t)__half_as_ushort(h1) << 16);
                    lv[j] = packh(x0 - __half2float(h0), x1 - __half2float(h1));
                }
                *(uint4*)(AH + c * 16) = make_uint4(hv[0], hv[1], hv[2], hv[3]);
                *(uint4*)(AL + c * 16) = make_uint4(lv[0], lv[1], lv[2], lv[3]);
            }
        }
        __syncthreads();

        // ---- GEMM: acc += Ah*B + Al*B ----
        float acc[2][8][4];
#pragma unroll
        for (int i = 0; i < 2; i++)
#pragma unroll
            for (int j = 0; j < 8; j++)
#pragma unroll
                for (int q = 0; q < 4; q++) acc[i][j][q] = 0.f;

#pragma unroll
        for (int k0 = 0; k0 < 128; k0 += 16) {
            uint32_t ah[2][4], al[2][4];
#pragma unroll
            for (int mt = 0; mt < 2; mt++) {
                uint32_t aoff = (uint32_t)((aro + mt * 16) * LDK + k0 + acol) * 2u;
                LDSM4(ah[mt], base + OFF_AH + aoff);
                LDSM4(al[mt], base + OFF_AL + aoff);
            }
#pragma unroll
            for (int np = 0; np < 4; np++) {
                uint32_t boff = (uint32_t)((bro + np * 16) * LDK + k0 + bcol) * 2u;
                uint32_t bh[4];
                LDSM4(bh, base + OFF_B + boff);
#pragma unroll
                for (int mt = 0; mt < 2; mt++) {
                    MMA16816(acc[mt][np * 2], ah[mt], bh[0], bh[1]);
                    MMA16816(acc[mt][np * 2], al[mt], bh[0], bh[1]);
                    MMA16816(acc[mt][np * 2 + 1], ah[mt], bh[2], bh[3]);
                    MMA16816(acc[mt][np * 2 + 1], al[mt], bh[2], bh[3]);
                }
            }
        }

#pragma unroll
        for (int mt = 0; mt < 2; mt++) {
            float pA = 0.f, pB = 0.f;
#pragma unroll
            for (int nt = 0; nt < 8; nt++) {
                int c0 = wn * 64 + nt * 8 + (lane & 3) * 2;
                float ba = b1s[c0], bb = b1s[c0 + 1];
                float wa = w2s[c0], wb = w2s[c0 + 1];
                pA = fmaf(fmaxf(acc[mt][nt][0] + ba, 0.f), wa, pA);
                pA = fmaf(fmaxf(acc[mt][nt][1] + bb, 0.f), wb, pA);
                pB = fmaf(fmaxf(acc[mt][nt][2] + ba, 0.f), wa, pB);
                pB = fmaf(fmaxf(acc[mt][nt][3] + bb, 0.f), wb, pB);
            }
            pA += __shfl_xor_sync(0xFFFFFFFF, pA, 1);
            pA += __shfl_xor_sync(0xFFFFFFFF, pA, 2);
            pB += __shfl_xor_sync(0xFFFFFFFF, pB, 1);
            pB += __shfl_xor_sync(0xFFFFFFFF, pB, 2);
            if ((lane & 3) == 0) {
                int r = wm * 32 + mt * 16 + (lane >> 2);
                predp[r * 2 + wn] = pA;
                predp[(r + 8) * 2 + wn] = pB;
            }
        }
        __syncthreads();
        if (t < 128) preds[t] = predp[2 * t] + predp[2 * t + 1] + b2v;
        __syncthreads();

        if (t < 32) {
            int qy = qy0 + (t >> 2);
            int qx = qx0 + (t & 3);
            int m0 = t * 4;
            float a0 = fabsf(relys[m0 + 0] * relxs[m0 + 0]) + 1e-9f;
            float a1 = fabsf(relys[m0 + 1] * relxs[m0 + 1]) + 1e-9f;
            float a2 = fabsf(relys[m0 + 2] * relxs[m0 + 2]) + 1e-9f;
            float a3 = fabsf(relys[m0 + 3] * relxs[m0 + 3]) + 1e-9f;
            float num = preds[m0 + 0] * a3 + preds[m0 + 1] * a2
                      + preds[m0 + 2] * a1 + preds[m0 + 3] * a0;
            out[qy * QRES + qx] = num / (a0 + a1 + a2 + a3);
        }
        __syncthreads();
    }
}

// ---------------------------------------------------------------------------
extern "C" void kernel_launch(void* const* d_in, const int* in_sizes, int n_in,
                              void* d_out, int out_size) {
    const float* feats2  = (const float*)d_in[0];
    const float* feats4  = (const float*)d_in[1];
    const float* feats32 = (const float*)d_in[2];
    const float* coords  = (const float*)d_in[3];
    const float* w2c  = (const float*)d_in[4];
    const float* s2c  = (const float*)d_in[5];
    const float* b2c  = (const float*)d_in[6];
    const float* w4c  = (const float*)d_in[7];
    const float* s4c  = (const float*)d_in[8];
    const float* b4c  = (const float*)d_in[9];
    const float* w32c = (const float*)d_in[10];
    const float* s32c = (const float*)d_in[11];
    const float* b32c = (const float*)d_in[12];
    const float* wf   = (const float*)d_in[13];
    const float* sf   = (const float*)d_in[14];
    const float* bf   = (const float*)d_in[15];
    const float* mw0  = (const float*)d_in[16];
    const float* mb0  = (const float*)d_in[17];
    const float* mw1  = (const float*)d_in[18];
    const float* mb1  = (const float*)d_in[19];
    const float* mw2  = (const float*)d_in[20];
    const float* mb2  = (const float*)d_in[21];
    float* out = (float*)d_out;

    float *catp, *a4p, *a32p;
    cudaGetSymbolAddress((void**)&catp,  g_cat);
    cudaGetSymbolAddress((void**)&a4p,   g_a4);
    cudaGetSymbolAddress((void**)&a32p,  g_a32);

    // launch order chosen so ncu (-s 5 -c 1) captures conv3x3g_kernel (idx 5)
    prep_kernel<<<(WF_N + W0_N + W1_N + 255) / 256, 256>>>(wf, mw0, mw1);   // 0
    conv1x1_kernel<<<128, 128>>>(feats4,  w4c,  s4c,  b4c,  a4p, 128 * 128, 128, 32, 0);  // 1
    conv1x1_kernel<<<2,   128>>>(feats32, w32c, s32c, b32c, a32p, 16 * 16, 256, 32, 0);   // 2
    upsample_kernel<<<(256 * 256 * 64) / 256, 256>>>();                     // 3
    conv1x1_kernel<<<512, 128>>>(feats2,  w2c,  s2c,  b2c,  catp, 256 * 256, 64, 96, 0);  // 4

    cudaFuncSetAttribute(conv3x3g_kernel, cudaFuncAttributeMaxDynamicSharedMemorySize,
                         CSM_TOTAL);
    conv3x3g_kernel<<<dim3(16, 32), 256, CSM_TOTAL>>>(sf, bf, mb0);         // 5

    cudaFuncSetAttribute(query_mma_kernel, cudaFuncAttributeMaxDynamicSharedMemorySize,
                         QSM_TOTAL);
    query_mma_kernel<<<1024, 256, QSM_TOTAL>>>(coords, mw0, mb1, mw2, mb2, out);  // 6

    (void)in_sizes; (void)n_in; (void)out_size;
}